// round 1
// baseline (speedup 1.0000x reference)
#include <cuda_runtime.h>

#define N_NODES 200000
#define N_EDGES 400000
#define D 128
#define NLAYER 5
#define AVC 100
#define BVC 10
#define BN_EPS 1e-5f

// ---------------- scratch (static device globals; no allocation) ----------------
__device__ float g_h[(size_t)N_NODES * D];     // h_prev
__device__ float g_hl[(size_t)N_NODES * D];    // linear output
__device__ float g_out[(size_t)N_NODES * D];   // aggregated output (pre-BN)
__device__ float g_edge[(size_t)N_EDGES * D];  // bond embeddings
__device__ float g_deg[N_NODES];
__device__ float g_norm[N_EDGES];
__device__ float g_stats[2 * D];               // sum, sumsq
__device__ float g_bn[2 * D];                  // scale, shift

// ---------------- encoders ----------------
__global__ void encode_atoms_kernel(const int* __restrict__ x,
                                    const float* __restrict__ at,
                                    float* __restrict__ total) {
    int n = blockIdx.x;
    int d = threadIdx.x;
    float s = 0.f;
#pragma unroll
    for (int c = 0; c < 9; c++) {
        int idx = __ldg(&x[n * 9 + c]);
        s += __ldg(&at[((size_t)c * AVC + idx) * D + d]);
    }
    g_h[(size_t)n * D + d] = s;
    total[(size_t)n * D + d] = s;   // total starts as h
}

__global__ void encode_bonds_kernel(const int* __restrict__ ea,
                                    const float* __restrict__ bt) {
    int e = blockIdx.x;
    int d = threadIdx.x;
    float s = 0.f;
#pragma unroll
    for (int c = 0; c < 3; c++) {
        int idx = __ldg(&ea[e * 3 + c]);
        s += __ldg(&bt[((size_t)c * BVC + idx) * D + d]);
    }
    g_edge[(size_t)e * D + d] = s;
}

// ---------------- degree / norm ----------------
__global__ void deg_init_kernel() {
    int i = blockIdx.x * blockDim.x + threadIdx.x;
    if (i < N_NODES) g_deg[i] = 1.f;
}

__global__ void deg_acc_kernel(const int* __restrict__ row) {
    for (int e = blockIdx.x * blockDim.x + threadIdx.x; e < N_EDGES;
         e += gridDim.x * blockDim.x)
        atomicAdd(&g_deg[row[e]], 1.f);
}

__global__ void norm_kernel(const int* __restrict__ row, const int* __restrict__ col) {
    int e = blockIdx.x * blockDim.x + threadIdx.x;
    if (e < N_EDGES)
        g_norm[e] = rsqrtf(g_deg[row[e]]) * rsqrtf(g_deg[col[e]]);
}

// ---------------- GEMM: hl = h @ W^T + b ; out = relu(hl + root)/deg ----------------
// 128x128 output tile, K=128 in chunks of 32, 256 threads, 8x8 per thread.
__global__ __launch_bounds__(256, 2)
void gemm_kernel(const float* __restrict__ Wl, const float* __restrict__ bias,
                 const float* __restrict__ root) {
    __shared__ float shA[32 * 132];  // [k][m], padded stride
    __shared__ float shB[32 * 132];  // [k][j]
    const int tid = threadIdx.x;
    const int m0 = blockIdx.x * 128;
    const int tm = (tid >> 4) * 8;
    const int tn = (tid & 15) * 8;
    const int lr = tid >> 3;        // 0..31
    const int lc = (tid & 7) * 4;   // 0,4,...,28

    float acc[8][8];
#pragma unroll
    for (int i = 0; i < 8; i++)
#pragma unroll
        for (int j = 0; j < 8; j++) acc[i][j] = 0.f;

    for (int k0 = 0; k0 < 128; k0 += 32) {
#pragma unroll
        for (int i = 0; i < 4; i++) {
            int m = m0 + lr + i * 32;
            float4 v = make_float4(0.f, 0.f, 0.f, 0.f);
            if (m < N_NODES) v = *(const float4*)&g_h[(size_t)m * D + k0 + lc];
            shA[(lc + 0) * 132 + lr + i * 32] = v.x;
            shA[(lc + 1) * 132 + lr + i * 32] = v.y;
            shA[(lc + 2) * 132 + lr + i * 32] = v.z;
            shA[(lc + 3) * 132 + lr + i * 32] = v.w;
        }
#pragma unroll
        for (int i = 0; i < 4; i++) {
            int j = lr + i * 32;
            float4 v = *(const float4*)&Wl[j * 128 + k0 + lc];
            shB[(lc + 0) * 132 + j] = v.x;
            shB[(lc + 1) * 132 + j] = v.y;
            shB[(lc + 2) * 132 + j] = v.z;
            shB[(lc + 3) * 132 + j] = v.w;
        }
        __syncthreads();
#pragma unroll
        for (int kk = 0; kk < 32; kk++) {
            float4 a0 = *(const float4*)&shA[kk * 132 + tm];
            float4 a1 = *(const float4*)&shA[kk * 132 + tm + 4];
            float4 b0 = *(const float4*)&shB[kk * 132 + tn];
            float4 b1 = *(const float4*)&shB[kk * 132 + tn + 4];
            float a[8] = {a0.x, a0.y, a0.z, a0.w, a1.x, a1.y, a1.z, a1.w};
            float b[8] = {b0.x, b0.y, b0.z, b0.w, b1.x, b1.y, b1.z, b1.w};
#pragma unroll
            for (int i = 0; i < 8; i++)
#pragma unroll
                for (int j = 0; j < 8; j++) acc[i][j] += a[i] * b[j];
        }
        __syncthreads();
    }

    float bs[8], rt[8];
#pragma unroll
    for (int j = 0; j < 8; j++) {
        bs[j] = __ldg(&bias[tn + j]);
        rt[j] = __ldg(&root[tn + j]);
    }
#pragma unroll
    for (int i = 0; i < 8; i++) {
        int m = m0 + tm + i;
        if (m < N_NODES) {
            float inv = 1.f / g_deg[m];
            float v[8], ob[8];
#pragma unroll
            for (int j = 0; j < 8; j++) {
                v[j] = acc[i][j] + bs[j];
                ob[j] = fmaxf(v[j] + rt[j], 0.f) * inv;
            }
            *(float4*)&g_hl[(size_t)m * D + tn]      = make_float4(v[0], v[1], v[2], v[3]);
            *(float4*)&g_hl[(size_t)m * D + tn + 4]  = make_float4(v[4], v[5], v[6], v[7]);
            *(float4*)&g_out[(size_t)m * D + tn]     = make_float4(ob[0], ob[1], ob[2], ob[3]);
            *(float4*)&g_out[(size_t)m * D + tn + 4] = make_float4(ob[4], ob[5], ob[6], ob[7]);
        }
    }
}

// ---------------- message + scatter: out[col] += norm * relu(hl[row] + edge_emb) ----------------
__global__ void message_kernel(const int* __restrict__ row, const int* __restrict__ col) {
    int e = blockIdx.x;
    int d = threadIdx.x;
    int r = __ldg(&row[e]);
    int c = __ldg(&col[e]);
    float nm = g_norm[e];
    float v = g_hl[(size_t)r * D + d] + g_edge[(size_t)e * D + d];
    v = fmaxf(v, 0.f) * nm;
    atomicAdd(&g_out[(size_t)c * D + d], v);
}

// ---------------- batch-norm stats / params / finalize ----------------
__global__ void zero_stats_kernel() {
    g_stats[threadIdx.x] = 0.f;   // blockDim = 256 = 2*D
}

__global__ void stats_kernel() {
    int d = threadIdx.x;
    float s = 0.f, sq = 0.f;
    for (int n = blockIdx.x; n < N_NODES; n += gridDim.x) {
        float v = g_out[(size_t)n * D + d];
        s += v;
        sq += v * v;
    }
    atomicAdd(&g_stats[d], s);
    atomicAdd(&g_stats[D + d], sq);
}

__global__ void bn_kernel(const float* __restrict__ gamma, const float* __restrict__ beta) {
    int d = threadIdx.x;
    float mean = g_stats[d] * (1.f / N_NODES);
    float var = g_stats[D + d] * (1.f / N_NODES) - mean * mean;
    float sc = __ldg(&gamma[d]) * rsqrtf(var + BN_EPS);
    g_bn[d] = sc;
    g_bn[D + d] = __ldg(&beta[d]) - mean * sc;
}

__global__ void finalize_kernel(float* __restrict__ total, int do_relu) {
    int d = threadIdx.x;
    float sc = g_bn[d], sh = g_bn[D + d];
    for (int n = blockIdx.x; n < N_NODES; n += gridDim.x) {
        size_t idx = (size_t)n * D + d;
        float v = g_out[idx] * sc + sh;
        if (do_relu) v = fmaxf(v, 0.f);
        total[idx] += v;
        g_h[idx] = v;
    }
}

// ---------------- launch ----------------
extern "C" void kernel_launch(void* const* d_in, const int* in_sizes, int n_in,
                              void* d_out, int out_size) {
    const int* x     = (const int*)d_in[0];
    const int* ei    = (const int*)d_in[1];
    const int* row   = ei;            // edge_index[0] : source j
    const int* col   = ei + N_EDGES;  // edge_index[1] : target i
    const int* ea    = (const int*)d_in[2];
    const float* at  = (const float*)d_in[3];
    const float* bt  = (const float*)d_in[4];
    const float* W   = (const float*)d_in[5];
    const float* b   = (const float*)d_in[6];
    const float* root  = (const float*)d_in[7];
    const float* gamma = (const float*)d_in[8];
    const float* beta  = (const float*)d_in[9];
    float* total = (float*)d_out;

    encode_atoms_kernel<<<N_NODES, 128>>>(x, at, total);
    encode_bonds_kernel<<<N_EDGES, 128>>>(ea, bt);
    deg_init_kernel<<<(N_NODES + 255) / 256, 256>>>();
    deg_acc_kernel<<<1024, 256>>>(row);
    norm_kernel<<<(N_EDGES + 255) / 256, 256>>>(row, col);

    for (int l = 0; l < NLAYER; l++) {
        gemm_kernel<<<(N_NODES + 127) / 128, 256>>>(
            W + (size_t)l * D * D, b + (size_t)l * D, root + (size_t)l * D);
        message_kernel<<<N_EDGES, 128>>>(row, col);
        zero_stats_kernel<<<1, 256>>>();
        stats_kernel<<<1024, 128>>>();
        bn_kernel<<<1, 128>>>(gamma + (size_t)l * D, beta + (size_t)l * D);
        finalize_kernel<<<2048, 128>>>(total, l < NLAYER - 1 ? 1 : 0);
    }
}

// round 4
// speedup vs baseline: 1.6879x; 1.6879x over previous
#include <cuda_runtime.h>
#include <cstdint>

#define N_NODES 200000
#define N_EDGES 400000
#define D 128
#define NLAYER 5
#define AVC 100
#define BVC 10
#define BN_EPS 1e-5f

// ---------------- scratch (static device globals; no allocation) ----------------
__device__ float g_hl[(size_t)N_NODES * D];    // linear output
__device__ float g_out[(size_t)N_NODES * D];   // aggregated output (pre-BN) / h carrier
__device__ float g_h0[(size_t)N_NODES * D];    // encoder output (layer-0 input)
__device__ float g_edge[(size_t)N_EDGES * D];  // bond embeddings
__device__ float g_deg[N_NODES];
__device__ float g_norm[N_EDGES];
__device__ float g_stats[2 * D];               // sum, sumsq
__device__ float g_bn[2 * D];                  // scale, shift

// ---------------- helpers ----------------
__device__ __forceinline__ uint32_t f2tf32(float f) {
    uint32_t r;
    asm("cvt.rna.tf32.f32 %0, %1;" : "=r"(r) : "f"(f));
    return r;
}

__device__ __forceinline__ void mma_tf32(float* d, const uint32_t* a, const uint32_t* b) {
    asm volatile(
        "mma.sync.aligned.m16n8k8.row.col.f32.tf32.tf32.f32 "
        "{%0,%1,%2,%3}, {%4,%5,%6,%7}, {%8,%9}, {%0,%1,%2,%3};\n"
        : "+f"(d[0]), "+f"(d[1]), "+f"(d[2]), "+f"(d[3])
        : "r"(a[0]), "r"(a[1]), "r"(a[2]), "r"(a[3]), "r"(b[0]), "r"(b[1]));
}

// ---------------- encoders (float4, 4 items per 128-thread block) ----------------
__global__ void encode_atoms_kernel(const int* __restrict__ x,
                                    const float* __restrict__ at,
                                    float* __restrict__ total) {
    int n = blockIdx.x * 4 + (threadIdx.x >> 5);
    if (n >= N_NODES) return;
    int d4 = (threadIdx.x & 31) * 4;
    float4 s = make_float4(0.f, 0.f, 0.f, 0.f);
#pragma unroll
    for (int c = 0; c < 9; c++) {
        int idx = __ldg(&x[n * 9 + c]);
        float4 v = *(const float4*)&at[((size_t)c * AVC + idx) * D + d4];
        s.x += v.x; s.y += v.y; s.z += v.z; s.w += v.w;
    }
    *(float4*)&g_h0[(size_t)n * D + d4] = s;
    *(float4*)&total[(size_t)n * D + d4] = s;
}

__global__ void encode_bonds_kernel(const int* __restrict__ ea,
                                    const float* __restrict__ bt) {
    int e = blockIdx.x * 4 + (threadIdx.x >> 5);
    if (e >= N_EDGES) return;
    int d4 = (threadIdx.x & 31) * 4;
    float4 s = make_float4(0.f, 0.f, 0.f, 0.f);
#pragma unroll
    for (int c = 0; c < 3; c++) {
        int idx = __ldg(&ea[e * 3 + c]);
        float4 v = *(const float4*)&bt[((size_t)c * BVC + idx) * D + d4];
        s.x += v.x; s.y += v.y; s.z += v.z; s.w += v.w;
    }
    *(float4*)&g_edge[(size_t)e * D + d4] = s;
}

// ---------------- degree / norm ----------------
__global__ void deg_kernel(const int* __restrict__ row) {
    int stride = gridDim.x * blockDim.x;
    for (int i = blockIdx.x * blockDim.x + threadIdx.x; i < N_NODES; i += stride)
        g_deg[i] = 1.f;
}

__global__ void deg_acc_kernel(const int* __restrict__ row) {
    for (int e = blockIdx.x * blockDim.x + threadIdx.x; e < N_EDGES;
         e += gridDim.x * blockDim.x)
        atomicAdd(&g_deg[row[e]], 1.f);
}

__global__ void norm_kernel(const int* __restrict__ row, const int* __restrict__ col) {
    int e = blockIdx.x * blockDim.x + threadIdx.x;
    if (e < N_EDGES)
        g_norm[e] = rsqrtf(g_deg[row[e]]) * rsqrtf(g_deg[col[e]]);
}

// ---------------- GEMM (tf32 tensor cores, 3-term split) ----------------
// hl = bnrelu(A) @ W^T + b ; g_out = relu(hl + root)/deg  (scatter base term)
// Block: 128 rows x 128 cols, 256 threads (8 warps, 2x4 warp grid, 64x32 per warp).
// bn_mode==0: A = g_h0, no BN. bn_mode==1: A = g_out with BN+relu applied on load.
__global__ __launch_bounds__(256, 2)
void gemm_tc_kernel(int bn_mode,
                    const float* __restrict__ Wl, const float* __restrict__ bias,
                    const float* __restrict__ root) {
    __shared__ uint32_t shA[128 * 40];  // [row][2*col + hi/lo], pad to 40 words
    __shared__ uint32_t shB[128 * 40];  // [n][2*col + hi/lo]

    const float* A = bn_mode ? g_out : g_h0;

    const int tid = threadIdx.x;
    const int m0 = blockIdx.x * 128;
    const int lane = tid & 31, grp = lane >> 2, tig = lane & 3;
    const int wid = tid >> 5;
    const int wm = (wid & 1) * 64;
    const int wn = (wid >> 1) * 32;

    float acc[4][4][4];
#pragma unroll
    for (int i = 0; i < 4; i++)
#pragma unroll
        for (int j = 0; j < 4; j++)
#pragma unroll
            for (int k = 0; k < 4; k++) acc[i][j][k] = 0.f;

    for (int k0 = 0; k0 < 128; k0 += 16) {
        // stage A (128x16) with optional BN+relu, split to tf32 hi/lo
#pragma unroll
        for (int it = 0; it < 2; it++) {
            int f = tid + it * 256;          // float4 index, 512 total
            int r = f >> 2;
            int c4 = (f & 3) * 4;
            int m = m0 + r;
            float4 v = make_float4(0.f, 0.f, 0.f, 0.f);
            if (m < N_NODES) v = *(const float4*)&A[(size_t)m * D + k0 + c4];
            if (bn_mode) {
                float4 sc = *(const float4*)&g_bn[k0 + c4];
                float4 sh = *(const float4*)&g_bn[D + k0 + c4];
                v.x = fmaxf(v.x * sc.x + sh.x, 0.f);
                v.y = fmaxf(v.y * sc.y + sh.y, 0.f);
                v.z = fmaxf(v.z * sc.z + sh.z, 0.f);
                v.w = fmaxf(v.w * sc.w + sh.w, 0.f);
            }
            uint32_t* p = &shA[r * 40 + c4 * 2];
            float e[4] = {v.x, v.y, v.z, v.w};
#pragma unroll
            for (int q = 0; q < 4; q++) {
                uint32_t hi = f2tf32(e[q]);
                float lo = e[q] - __uint_as_float(hi);
                p[2 * q] = hi;
                p[2 * q + 1] = f2tf32(lo);
            }
        }
        // stage B = W[n][k] (128x16)
#pragma unroll
        for (int it = 0; it < 2; it++) {
            int f = tid + it * 256;
            int r = f >> 2;
            int c4 = (f & 3) * 4;
            float4 v = *(const float4*)&Wl[r * D + k0 + c4];
            uint32_t* p = &shB[r * 40 + c4 * 2];
            float e[4] = {v.x, v.y, v.z, v.w};
#pragma unroll
            for (int q = 0; q < 4; q++) {
                uint32_t hi = f2tf32(e[q]);
                float lo = e[q] - __uint_as_float(hi);
                p[2 * q] = hi;
                p[2 * q + 1] = f2tf32(lo);
            }
        }
        __syncthreads();

#pragma unroll
        for (int ks = 0; ks < 16; ks += 8) {
            uint32_t bh[4][2], bl[4][2];
#pragma unroll
            for (int j = 0; j < 4; j++) {
                int n = wn + j * 8 + grp;
                uint2 p0 = *(const uint2*)&shB[n * 40 + (ks + tig) * 2];
                uint2 p1 = *(const uint2*)&shB[n * 40 + (ks + tig + 4) * 2];
                bh[j][0] = p0.x; bl[j][0] = p0.y;
                bh[j][1] = p1.x; bl[j][1] = p1.y;
            }
#pragma unroll
            for (int i = 0; i < 4; i++) {
                int r0 = wm + i * 16 + grp;
                uint2 q0 = *(const uint2*)&shA[r0 * 40 + (ks + tig) * 2];
                uint2 q1 = *(const uint2*)&shA[(r0 + 8) * 40 + (ks + tig) * 2];
                uint2 q2 = *(const uint2*)&shA[r0 * 40 + (ks + tig + 4) * 2];
                uint2 q3 = *(const uint2*)&shA[(r0 + 8) * 40 + (ks + tig + 4) * 2];
                uint32_t ah[4] = {q0.x, q1.x, q2.x, q3.x};
                uint32_t al[4] = {q0.y, q1.y, q2.y, q3.y};
#pragma unroll
                for (int j = 0; j < 4; j++) {
                    mma_tf32(acc[i][j], ah, bh[j]);
                    mma_tf32(acc[i][j], al, bh[j]);
                    mma_tf32(acc[i][j], ah, bl[j]);
                }
            }
        }
        __syncthreads();
    }

    // epilogue: hoist per-column constants out of the row loop
    float bs[4][2], rt[4][2];
#pragma unroll
    for (int j = 0; j < 4; j++) {
        int col = wn + j * 8 + tig * 2;
        bs[j][0] = __ldg(&bias[col]);     bs[j][1] = __ldg(&bias[col + 1]);
        rt[j][0] = __ldg(&root[col]);     rt[j][1] = __ldg(&root[col + 1]);
    }
#pragma unroll
    for (int i = 0; i < 4; i++) {
        int rbase = m0 + wm + i * 16 + grp;
#pragma unroll
        for (int half = 0; half < 2; half++) {
            int m = rbase + half * 8;
            if (m >= N_NODES) continue;
            float inv = 1.f / g_deg[m];
#pragma unroll
            for (int j = 0; j < 4; j++) {
                int col = wn + j * 8 + tig * 2;
                float v0 = acc[i][j][half * 2 + 0] + bs[j][0];
                float v1 = acc[i][j][half * 2 + 1] + bs[j][1];
                *(float2*)&g_hl[(size_t)m * D + col] = make_float2(v0, v1);
                float o0 = fmaxf(v0 + rt[j][0], 0.f) * inv;
                float o1 = fmaxf(v1 + rt[j][1], 0.f) * inv;
                *(float2*)&g_out[(size_t)m * D + col] = make_float2(o0, o1);
            }
        }
    }
}

// ---------------- message + scatter: out[col] += norm * relu(hl[row] + edge_emb) ----------------
__global__ void message_kernel(const int* __restrict__ row, const int* __restrict__ col) {
    int e = blockIdx.x * 8 + (threadIdx.x >> 5);
    if (e >= N_EDGES) return;
    int d4 = (threadIdx.x & 31) * 4;
    int r = __ldg(&row[e]);
    int c = __ldg(&col[e]);
    float nm = g_norm[e];
    float4 h = *(const float4*)&g_hl[(size_t)r * D + d4];
    float4 em = *(const float4*)&g_edge[(size_t)e * D + d4];
    float v0 = fmaxf(h.x + em.x, 0.f) * nm;
    float v1 = fmaxf(h.y + em.y, 0.f) * nm;
    float v2 = fmaxf(h.z + em.z, 0.f) * nm;
    float v3 = fmaxf(h.w + em.w, 0.f) * nm;
    float* o = &g_out[(size_t)c * D + d4];
    atomicAdd(o + 0, v0);
    atomicAdd(o + 1, v1);
    atomicAdd(o + 2, v2);
    atomicAdd(o + 3, v3);
}

// ---------------- batch-norm stats / params / finalize ----------------
__global__ void zero_stats_kernel() {
    g_stats[threadIdx.x] = 0.f;   // blockDim = 256 = 2*D
}

__global__ void stats_kernel() {
    int d = threadIdx.x;
    float s = 0.f, sq = 0.f;
    for (int n = blockIdx.x; n < N_NODES; n += gridDim.x) {
        float v = g_out[(size_t)n * D + d];
        s += v;
        sq += v * v;
    }
    atomicAdd(&g_stats[d], s);
    atomicAdd(&g_stats[D + d], sq);
}

__global__ void bn_kernel(const float* __restrict__ gamma, const float* __restrict__ beta) {
    int d = threadIdx.x;
    float mean = g_stats[d] * (1.f / N_NODES);
    float var = g_stats[D + d] * (1.f / N_NODES) - mean * mean;
    float sc = __ldg(&gamma[d]) * rsqrtf(var + BN_EPS);
    g_bn[d] = sc;
    g_bn[D + d] = __ldg(&beta[d]) - mean * sc;
}

// total += bn(g_out) (with relu except last layer). h for next layer is applied
// on the fly in the next GEMM's A-load, so no g_h stream.
__global__ void finalize_kernel(float* __restrict__ total, int do_relu) {
    int lane = threadIdx.x & 31;
    int warp = threadIdx.x >> 5;       // 8 warps = 8 rows per iter
    int d4 = lane * 4;
    float4 sc = *(const float4*)&g_bn[d4];
    float4 sh = *(const float4*)&g_bn[D + d4];
    for (int n = blockIdx.x * 8 + warp; n < N_NODES; n += gridDim.x * 8) {
        size_t idx = (size_t)n * D + d4;
        float4 v = *(const float4*)&g_out[idx];
        float4 t = *(const float4*)&total[idx];
        float w0 = v.x * sc.x + sh.x;
        float w1 = v.y * sc.y + sh.y;
        float w2 = v.z * sc.z + sh.z;
        float w3 = v.w * sc.w + sh.w;
        if (do_relu) {
            w0 = fmaxf(w0, 0.f); w1 = fmaxf(w1, 0.f);
            w2 = fmaxf(w2, 0.f); w3 = fmaxf(w3, 0.f);
        }
        t.x += w0; t.y += w1; t.z += w2; t.w += w3;
        *(float4*)&total[idx] = t;
    }
}

// ---------------- launch ----------------
extern "C" void kernel_launch(void* const* d_in, const int* in_sizes, int n_in,
                              void* d_out, int out_size) {
    const int* x     = (const int*)d_in[0];
    const int* ei    = (const int*)d_in[1];
    const int* row   = ei;            // edge_index[0] : source j
    const int* col   = ei + N_EDGES;  // edge_index[1] : target i
    const int* ea    = (const int*)d_in[2];
    const float* at  = (const float*)d_in[3];
    const float* bt  = (const float*)d_in[4];
    const float* W   = (const float*)d_in[5];
    const float* b   = (const float*)d_in[6];
    const float* root  = (const float*)d_in[7];
    const float* gamma = (const float*)d_in[8];
    const float* beta  = (const float*)d_in[9];
    float* total = (float*)d_out;

    encode_atoms_kernel<<<(N_NODES + 3) / 4, 128>>>(x, at, total);
    encode_bonds_kernel<<<(N_EDGES + 3) / 4, 128>>>(ea, bt);
    deg_kernel<<<1024, 256>>>(row);
    deg_acc_kernel<<<1024, 256>>>(row);
    norm_kernel<<<(N_EDGES + 255) / 256, 256>>>(row, col);

    for (int l = 0; l < NLAYER; l++) {
        gemm_tc_kernel<<<(N_NODES + 127) / 128, 256>>>(
            l == 0 ? 0 : 1,
            W + (size_t)l * D * D, b + (size_t)l * D, root + (size_t)l * D);
        message_kernel<<<(N_EDGES + 7) / 8, 256>>>(row, col);
        zero_stats_kernel<<<1, 256>>>();
        stats_kernel<<<1024, 128>>>();
        bn_kernel<<<1, 128>>>(gamma + (size_t)l * D, beta + (size_t)l * D);
        finalize_kernel<<<2048, 256>>>(total, l < NLAYER - 1 ? 1 : 0);
    }
}

// round 5
// speedup vs baseline: 2.3140x; 1.3709x over previous
#include <cuda_runtime.h>
#include <cstdint>

#define N_NODES 200000
#define N_EDGES 400000
#define D 128
#define NLAYER 5
#define AVC 100
#define BVC 10
#define BN_EPS 1e-5f

// ---------------- scratch (static device globals; no allocation) ----------------
__device__ float g_hl[(size_t)N_NODES * D];    // linear output
__device__ float g_out[(size_t)N_NODES * D];   // aggregated output (pre-BN) / h carrier
__device__ float g_h0[(size_t)N_NODES * D];    // encoder output (layer-0 input)
__device__ float g_edge[(size_t)N_EDGES * D];  // bond embeddings (CSR-permuted)
__device__ float g_deg[N_NODES];
__device__ float g_enorm[N_EDGES];             // norm per CSR slot
__device__ int   g_indeg[N_NODES];
__device__ int   g_off[N_NODES];               // CSR offsets (exclusive scan)
__device__ int   g_cursor[N_NODES];
__device__ int   g_bsum[1024];
__device__ int   g_src[N_EDGES];               // source node per CSR slot
__device__ int   g_eperm[N_EDGES];             // original edge id per CSR slot
__device__ float g_stats[2 * D];               // sum, sumsq
__device__ float g_bn[2 * D];                  // scale, shift

// ---------------- helpers ----------------
__device__ __forceinline__ uint32_t f2tf32(float f) {
    uint32_t r;
    asm("cvt.rna.tf32.f32 %0, %1;" : "=r"(r) : "f"(f));
    return r;
}

__device__ __forceinline__ void mma_tf32(float* d, const uint32_t* a, const uint32_t* b) {
    asm volatile(
        "mma.sync.aligned.m16n8k8.row.col.f32.tf32.tf32.f32 "
        "{%0,%1,%2,%3}, {%4,%5,%6,%7}, {%8,%9}, {%0,%1,%2,%3};\n"
        : "+f"(d[0]), "+f"(d[1]), "+f"(d[2]), "+f"(d[3])
        : "r"(a[0]), "r"(a[1]), "r"(a[2]), "r"(a[3]), "r"(b[0]), "r"(b[1]));
}

// ---------------- setup: degrees + CSR ----------------
__global__ void init_kernel() {
    int stride = gridDim.x * blockDim.x;
    for (int i = blockIdx.x * blockDim.x + threadIdx.x; i < N_NODES; i += stride) {
        g_deg[i] = 1.f;
        g_indeg[i] = 0;
    }
}

__global__ void deg_acc_kernel(const int* __restrict__ row) {
    for (int e = blockIdx.x * blockDim.x + threadIdx.x; e < N_EDGES;
         e += gridDim.x * blockDim.x)
        atomicAdd(&g_deg[row[e]], 1.f);
}

__global__ void indeg_acc_kernel(const int* __restrict__ col) {
    for (int e = blockIdx.x * blockDim.x + threadIdx.x; e < N_EDGES;
         e += gridDim.x * blockDim.x)
        atomicAdd(&g_indeg[col[e]], 1);
}

// block-level exclusive scan of g_indeg -> g_off (partial), block sums -> g_bsum
__global__ void scan1_kernel() {
    __shared__ int sh[256];
    int tid = threadIdx.x;
    int i = blockIdx.x * 256 + tid;
    int v = (i < N_NODES) ? g_indeg[i] : 0;
    sh[tid] = v;
    __syncthreads();
#pragma unroll
    for (int ofs = 1; ofs < 256; ofs <<= 1) {
        int t = (tid >= ofs) ? sh[tid - ofs] : 0;
        __syncthreads();
        sh[tid] += t;
        __syncthreads();
    }
    if (i < N_NODES) g_off[i] = sh[tid] - v;  // exclusive
    if (tid == 255) g_bsum[blockIdx.x] = sh[255];
}

__global__ void scan2_kernel(int nblk) {   // single block of 1024
    __shared__ int sh[1024];
    int tid = threadIdx.x;
    int v = (tid < nblk) ? g_bsum[tid] : 0;
    sh[tid] = v;
    __syncthreads();
#pragma unroll
    for (int ofs = 1; ofs < 1024; ofs <<= 1) {
        int t = (tid >= ofs) ? sh[tid - ofs] : 0;
        __syncthreads();
        sh[tid] += t;
        __syncthreads();
    }
    if (tid < nblk) g_bsum[tid] = sh[tid] - v;  // exclusive
}

__global__ void scan3_kernel() {
    int i = blockIdx.x * 256 + threadIdx.x;
    if (i < N_NODES) {
        int o = g_off[i] + g_bsum[blockIdx.x];
        g_off[i] = o;
        g_cursor[i] = o;
    }
}

__global__ void fill_kernel(const int* __restrict__ row, const int* __restrict__ col) {
    for (int e = blockIdx.x * blockDim.x + threadIdx.x; e < N_EDGES;
         e += gridDim.x * blockDim.x) {
        int r = row[e], c = col[e];
        int pos = atomicAdd(&g_cursor[c], 1);
        g_src[pos] = r;
        g_eperm[pos] = e;
        g_enorm[pos] = rsqrtf(g_deg[r]) * rsqrtf(g_deg[c]);
    }
}

// ---------------- encoders ----------------
__global__ void encode_atoms_kernel(const int* __restrict__ x,
                                    const float* __restrict__ at,
                                    float* __restrict__ total) {
    int n = blockIdx.x * 4 + (threadIdx.x >> 5);
    if (n >= N_NODES) return;
    int d4 = (threadIdx.x & 31) * 4;
    float4 s = make_float4(0.f, 0.f, 0.f, 0.f);
#pragma unroll
    for (int c = 0; c < 9; c++) {
        int idx = __ldg(&x[n * 9 + c]);
        float4 v = *(const float4*)&at[((size_t)c * AVC + idx) * D + d4];
        s.x += v.x; s.y += v.y; s.z += v.z; s.w += v.w;
    }
    *(float4*)&g_h0[(size_t)n * D + d4] = s;
    *(float4*)&total[(size_t)n * D + d4] = s;
}

// bond embeddings written in CSR-permuted order
__global__ void encode_bonds_kernel(const int* __restrict__ ea,
                                    const float* __restrict__ bt) {
    int pos = blockIdx.x * 4 + (threadIdx.x >> 5);
    if (pos >= N_EDGES) return;
    int e = g_eperm[pos];
    int d4 = (threadIdx.x & 31) * 4;
    float4 s = make_float4(0.f, 0.f, 0.f, 0.f);
#pragma unroll
    for (int c = 0; c < 3; c++) {
        int idx = __ldg(&ea[e * 3 + c]);
        float4 v = *(const float4*)&bt[((size_t)c * BVC + idx) * D + d4];
        s.x += v.x; s.y += v.y; s.z += v.z; s.w += v.w;
    }
    *(float4*)&g_edge[(size_t)pos * D + d4] = s;
}

// ---------------- GEMM (tf32 tensor cores, 3-term split, reg prefetch) ----------------
__global__ __launch_bounds__(256, 2)
void gemm_tc_kernel(int bn_mode,
                    const float* __restrict__ Wl, const float* __restrict__ bias,
                    const float* __restrict__ root) {
    __shared__ uint32_t shA[128 * 40];
    __shared__ uint32_t shB[128 * 40];

    const float* A = bn_mode ? g_out : g_h0;

    const int tid = threadIdx.x;
    const int m0 = blockIdx.x * 128;
    const int lane = tid & 31, grp = lane >> 2, tig = lane & 3;
    const int wid = tid >> 5;
    const int wm = (wid & 1) * 64;
    const int wn = (wid >> 1) * 32;

    // staging coords for this thread (2 float4s per tensor per chunk)
    const int sr0 = tid >> 2,        sc0 = (tid & 3) * 4;
    const int sr1 = (tid + 256) >> 2, sc1 = ((tid + 256) & 3) * 4;

    float acc[4][4][4];
#pragma unroll
    for (int i = 0; i < 4; i++)
#pragma unroll
        for (int j = 0; j < 4; j++)
#pragma unroll
            for (int k = 0; k < 4; k++) acc[i][j][k] = 0.f;

    const float4 z4 = make_float4(0.f, 0.f, 0.f, 0.f);
    float4 ra[2], rb[2];
    {
        int m = m0 + sr0;
        ra[0] = (m < N_NODES) ? *(const float4*)&A[(size_t)m * D + sc0] : z4;
        m = m0 + sr1;
        ra[1] = (m < N_NODES) ? *(const float4*)&A[(size_t)m * D + sc1] : z4;
        rb[0] = *(const float4*)&Wl[sr0 * D + sc0];
        rb[1] = *(const float4*)&Wl[sr1 * D + sc1];
    }

    for (int k0 = 0; k0 < 128; k0 += 16) {
        // stage from registers into smem (with optional BN+relu on A)
#pragma unroll
        for (int it = 0; it < 2; it++) {
            int r  = it ? sr1 : sr0;
            int c4 = it ? sc1 : sc0;
            float4 v = ra[it];
            if (bn_mode) {
                float4 sc = *(const float4*)&g_bn[k0 + c4];
                float4 sh = *(const float4*)&g_bn[D + k0 + c4];
                v.x = fmaxf(v.x * sc.x + sh.x, 0.f);
                v.y = fmaxf(v.y * sc.y + sh.y, 0.f);
                v.z = fmaxf(v.z * sc.z + sh.z, 0.f);
                v.w = fmaxf(v.w * sc.w + sh.w, 0.f);
            }
            uint32_t* p = &shA[r * 40 + c4 * 2];
            float e[4] = {v.x, v.y, v.z, v.w};
#pragma unroll
            for (int q = 0; q < 4; q++) {
                uint32_t hi = f2tf32(e[q]);
                p[2 * q] = hi;
                p[2 * q + 1] = f2tf32(e[q] - __uint_as_float(hi));
            }
            float4 w = rb[it];
            uint32_t* pb = &shB[r * 40 + c4 * 2];
            float ew[4] = {w.x, w.y, w.z, w.w};
#pragma unroll
            for (int q = 0; q < 4; q++) {
                uint32_t hi = f2tf32(ew[q]);
                pb[2 * q] = hi;
                pb[2 * q + 1] = f2tf32(ew[q] - __uint_as_float(hi));
            }
        }
        __syncthreads();

        // prefetch next chunk while computing
        if (k0 + 16 < 128) {
            int kn = k0 + 16;
            int m = m0 + sr0;
            ra[0] = (m < N_NODES) ? *(const float4*)&A[(size_t)m * D + kn + sc0] : z4;
            m = m0 + sr1;
            ra[1] = (m < N_NODES) ? *(const float4*)&A[(size_t)m * D + kn + sc1] : z4;
            rb[0] = *(const float4*)&Wl[sr0 * D + kn + sc0];
            rb[1] = *(const float4*)&Wl[sr1 * D + kn + sc1];
        }

#pragma unroll
        for (int ks = 0; ks < 16; ks += 8) {
            uint32_t bh[4][2], bl[4][2];
#pragma unroll
            for (int j = 0; j < 4; j++) {
                int n = wn + j * 8 + grp;
                uint2 p0 = *(const uint2*)&shB[n * 40 + (ks + tig) * 2];
                uint2 p1 = *(const uint2*)&shB[n * 40 + (ks + tig + 4) * 2];
                bh[j][0] = p0.x; bl[j][0] = p0.y;
                bh[j][1] = p1.x; bl[j][1] = p1.y;
            }
#pragma unroll
            for (int i = 0; i < 4; i++) {
                int r0 = wm + i * 16 + grp;
                uint2 q0 = *(const uint2*)&shA[r0 * 40 + (ks + tig) * 2];
                uint2 q1 = *(const uint2*)&shA[(r0 + 8) * 40 + (ks + tig) * 2];
                uint2 q2 = *(const uint2*)&shA[r0 * 40 + (ks + tig + 4) * 2];
                uint2 q3 = *(const uint2*)&shA[(r0 + 8) * 40 + (ks + tig + 4) * 2];
                uint32_t ah[4] = {q0.x, q1.x, q2.x, q3.x};
                uint32_t al[4] = {q0.y, q1.y, q2.y, q3.y};
#pragma unroll
                for (int j = 0; j < 4; j++) {
                    mma_tf32(acc[i][j], ah, bh[j]);
                    mma_tf32(acc[i][j], al, bh[j]);
                    mma_tf32(acc[i][j], ah, bl[j]);
                }
            }
        }
        __syncthreads();
    }

    // epilogue
    float bs[4][2], rt[4][2];
#pragma unroll
    for (int j = 0; j < 4; j++) {
        int col = wn + j * 8 + tig * 2;
        bs[j][0] = __ldg(&bias[col]);  bs[j][1] = __ldg(&bias[col + 1]);
        rt[j][0] = __ldg(&root[col]);  rt[j][1] = __ldg(&root[col + 1]);
    }
#pragma unroll
    for (int i = 0; i < 4; i++) {
        int rbase = m0 + wm + i * 16 + grp;
#pragma unroll
        for (int half = 0; half < 2; half++) {
            int m = rbase + half * 8;
            if (m >= N_NODES) continue;
            float inv = 1.f / g_deg[m];
#pragma unroll
            for (int j = 0; j < 4; j++) {
                int col = wn + j * 8 + tig * 2;
                float v0 = acc[i][j][half * 2 + 0] + bs[j][0];
                float v1 = acc[i][j][half * 2 + 1] + bs[j][1];
                *(float2*)&g_hl[(size_t)m * D + col] = make_float2(v0, v1);
                float o0 = fmaxf(v0 + rt[j][0], 0.f) * inv;
                float o1 = fmaxf(v1 + rt[j][1], 0.f) * inv;
                *(float2*)&g_out[(size_t)m * D + col] = make_float2(o0, o1);
            }
        }
    }
}

// ---------------- gather message + fused BN stats ----------------
// out[n] = base[n] + sum_{k in csr(n)} enorm[k] * relu(hl[src[k]] + edge[k])
// plus block-reduced sum/sumsq accumulation into g_stats.
__global__ __launch_bounds__(256)
void gather_kernel() {
    __shared__ float shs[8 * 128];
    __shared__ float shq[8 * 128];
    int wid = threadIdx.x >> 5, lane = threadIdx.x & 31;
    int d4 = lane * 4;
    float4 sum = make_float4(0.f, 0.f, 0.f, 0.f);
    float4 sq  = make_float4(0.f, 0.f, 0.f, 0.f);

    for (int n = blockIdx.x * 8 + wid; n < N_NODES; n += gridDim.x * 8) {
        int start = g_off[n];
        int end = (n < N_NODES - 1) ? g_off[n + 1] : N_EDGES;
        float4 acc = *(const float4*)&g_out[(size_t)n * D + d4];
        for (int k = start; k < end; k++) {
            int s = g_src[k];
            float nm = g_enorm[k];
            float4 h = *(const float4*)&g_hl[(size_t)s * D + d4];
            float4 em = *(const float4*)&g_edge[(size_t)k * D + d4];
            acc.x += fmaxf(h.x + em.x, 0.f) * nm;
            acc.y += fmaxf(h.y + em.y, 0.f) * nm;
            acc.z += fmaxf(h.z + em.z, 0.f) * nm;
            acc.w += fmaxf(h.w + em.w, 0.f) * nm;
        }
        *(float4*)&g_out[(size_t)n * D + d4] = acc;
        sum.x += acc.x; sum.y += acc.y; sum.z += acc.z; sum.w += acc.w;
        sq.x += acc.x * acc.x; sq.y += acc.y * acc.y;
        sq.z += acc.z * acc.z; sq.w += acc.w * acc.w;
    }

    *(float4*)&shs[wid * 128 + d4] = sum;
    *(float4*)&shq[wid * 128 + d4] = sq;
    __syncthreads();
    if (threadIdx.x < 128) {
        float s = 0.f, q = 0.f;
#pragma unroll
        for (int w = 0; w < 8; w++) {
            s += shs[w * 128 + threadIdx.x];
            q += shq[w * 128 + threadIdx.x];
        }
        atomicAdd(&g_stats[threadIdx.x], s);
        atomicAdd(&g_stats[D + threadIdx.x], q);
    }
}

// ---------------- batch-norm params / finalize ----------------
__global__ void zero_stats_kernel() {
    g_stats[threadIdx.x] = 0.f;   // blockDim = 256 = 2*D
}

__global__ void bn_kernel(const float* __restrict__ gamma, const float* __restrict__ beta) {
    int d = threadIdx.x;
    float mean = g_stats[d] * (1.f / N_NODES);
    float var = g_stats[D + d] * (1.f / N_NODES) - mean * mean;
    float sc = __ldg(&gamma[d]) * rsqrtf(var + BN_EPS);
    g_bn[d] = sc;
    g_bn[D + d] = __ldg(&beta[d]) - mean * sc;
}

__global__ void finalize_kernel(float* __restrict__ total, int do_relu) {
    int lane = threadIdx.x & 31;
    int warp = threadIdx.x >> 5;
    int d4 = lane * 4;
    float4 sc = *(const float4*)&g_bn[d4];
    float4 sh = *(const float4*)&g_bn[D + d4];
    for (int n = blockIdx.x * 8 + warp; n < N_NODES; n += gridDim.x * 8) {
        size_t idx = (size_t)n * D + d4;
        float4 v = *(const float4*)&g_out[idx];
        float4 t = *(const float4*)&total[idx];
        float w0 = v.x * sc.x + sh.x;
        float w1 = v.y * sc.y + sh.y;
        float w2 = v.z * sc.z + sh.z;
        float w3 = v.w * sc.w + sh.w;
        if (do_relu) {
            w0 = fmaxf(w0, 0.f); w1 = fmaxf(w1, 0.f);
            w2 = fmaxf(w2, 0.f); w3 = fmaxf(w3, 0.f);
        }
        t.x += w0; t.y += w1; t.z += w2; t.w += w3;
        *(float4*)&total[idx] = t;
    }
}

// ---------------- launch ----------------
extern "C" void kernel_launch(void* const* d_in, const int* in_sizes, int n_in,
                              void* d_out, int out_size) {
    const int* x     = (const int*)d_in[0];
    const int* ei    = (const int*)d_in[1];
    const int* row   = ei;            // edge_index[0] : source j
    const int* col   = ei + N_EDGES;  // edge_index[1] : target i
    const int* ea    = (const int*)d_in[2];
    const float* at  = (const float*)d_in[3];
    const float* bt  = (const float*)d_in[4];
    const float* W   = (const float*)d_in[5];
    const float* b   = (const float*)d_in[6];
    const float* root  = (const float*)d_in[7];
    const float* gamma = (const float*)d_in[8];
    const float* beta  = (const float*)d_in[9];
    float* total = (float*)d_out;

    const int nscan = (N_NODES + 255) / 256;   // 782

    init_kernel<<<1024, 256>>>();
    deg_acc_kernel<<<1024, 256>>>(row);
    indeg_acc_kernel<<<1024, 256>>>(col);
    scan1_kernel<<<nscan, 256>>>();
    scan2_kernel<<<1, 1024>>>(nscan);
    scan3_kernel<<<nscan, 256>>>();
    fill_kernel<<<1024, 256>>>(row, col);
    encode_atoms_kernel<<<(N_NODES + 3) / 4, 128>>>(x, at, total);
    encode_bonds_kernel<<<(N_EDGES + 3) / 4, 128>>>(ea, bt);

    for (int l = 0; l < NLAYER; l++) {
        gemm_tc_kernel<<<(N_NODES + 127) / 128, 256>>>(
            l == 0 ? 0 : 1,
            W + (size_t)l * D * D, b + (size_t)l * D, root + (size_t)l * D);
        zero_stats_kernel<<<1, 256>>>();
        gather_kernel<<<2048, 256>>>();
        bn_kernel<<<1, 128>>>(gamma + (size_t)l * D, beta + (size_t)l * D);
        finalize_kernel<<<2048, 256>>>(total, l < NLAYER - 1 ? 1 : 0);
    }
}

// round 6
// speedup vs baseline: 2.5572x; 1.1051x over previous
#include <cuda_runtime.h>
#include <cuda_fp16.h>
#include <cstdint>

#define N_NODES 200000
#define N_EDGES 400000
#define D 128
#define NLAYER 5
#define AVC 100
#define BVC 10
#define BN_EPS 1e-5f

// ---------------- scratch (static device globals; no allocation) ----------------
__device__ float g_hl[(size_t)N_NODES * D];    // linear output
__device__ float g_out[(size_t)N_NODES * D];   // aggregated output (pre-BN) / h carrier
__device__ float g_h0[(size_t)N_NODES * D];    // encoder output (layer-0 input)
__device__ __half g_edgeh[(size_t)N_EDGES * D]; // bond embeddings (CSR-permuted, fp16)
__device__ float g_deg[N_NODES];
__device__ float g_enorm[N_EDGES];             // norm per CSR slot
__device__ int   g_indeg[N_NODES];
__device__ int   g_off[N_NODES];               // CSR offsets (exclusive scan)
__device__ int   g_cursor[N_NODES];
__device__ int   g_bsum[1024];
__device__ int   g_src[N_EDGES];               // source node per CSR slot
__device__ int   g_eperm[N_EDGES];             // original edge id per CSR slot
__device__ float g_stats[2 * D];               // sum, sumsq
__device__ float g_bn[2 * D];                  // scale, shift

// ---------------- helpers ----------------
__device__ __forceinline__ uint32_t f2tf32(float f) {
    uint32_t r;
    asm("cvt.rna.tf32.f32 %0, %1;" : "=r"(r) : "f"(f));
    return r;
}

__device__ __forceinline__ void mma_tf32(float* d, const uint32_t* a, const uint32_t* b) {
    asm volatile(
        "mma.sync.aligned.m16n8k8.row.col.f32.tf32.tf32.f32 "
        "{%0,%1,%2,%3}, {%4,%5,%6,%7}, {%8,%9}, {%0,%1,%2,%3};\n"
        : "+f"(d[0]), "+f"(d[1]), "+f"(d[2]), "+f"(d[3])
        : "r"(a[0]), "r"(a[1]), "r"(a[2]), "r"(a[3]), "r"(b[0]), "r"(b[1]));
}

// ---------------- setup: degrees + CSR ----------------
__global__ void init_kernel() {
    int stride = gridDim.x * blockDim.x;
    for (int i = blockIdx.x * blockDim.x + threadIdx.x; i < N_NODES; i += stride) {
        g_deg[i] = 1.f;
        g_indeg[i] = 0;
    }
}

__global__ void deg_acc_kernel(const int* __restrict__ row) {
    for (int e = blockIdx.x * blockDim.x + threadIdx.x; e < N_EDGES;
         e += gridDim.x * blockDim.x)
        atomicAdd(&g_deg[row[e]], 1.f);
}

__global__ void indeg_acc_kernel(const int* __restrict__ col) {
    for (int e = blockIdx.x * blockDim.x + threadIdx.x; e < N_EDGES;
         e += gridDim.x * blockDim.x)
        atomicAdd(&g_indeg[col[e]], 1);
}

__global__ void scan1_kernel() {
    __shared__ int sh[256];
    int tid = threadIdx.x;
    int i = blockIdx.x * 256 + tid;
    int v = (i < N_NODES) ? g_indeg[i] : 0;
    sh[tid] = v;
    __syncthreads();
#pragma unroll
    for (int ofs = 1; ofs < 256; ofs <<= 1) {
        int t = (tid >= ofs) ? sh[tid - ofs] : 0;
        __syncthreads();
        sh[tid] += t;
        __syncthreads();
    }
    if (i < N_NODES) g_off[i] = sh[tid] - v;  // exclusive
    if (tid == 255) g_bsum[blockIdx.x] = sh[255];
}

__global__ void scan2_kernel(int nblk) {   // single block of 1024
    __shared__ int sh[1024];
    int tid = threadIdx.x;
    int v = (tid < nblk) ? g_bsum[tid] : 0;
    sh[tid] = v;
    __syncthreads();
#pragma unroll
    for (int ofs = 1; ofs < 1024; ofs <<= 1) {
        int t = (tid >= ofs) ? sh[tid - ofs] : 0;
        __syncthreads();
        sh[tid] += t;
        __syncthreads();
    }
    if (tid < nblk) g_bsum[tid] = sh[tid] - v;  // exclusive
}

__global__ void scan3_kernel() {
    int i = blockIdx.x * 256 + threadIdx.x;
    if (i < N_NODES) {
        int o = g_off[i] + g_bsum[blockIdx.x];
        g_off[i] = o;
        g_cursor[i] = o;
    }
}

__global__ void fill_kernel(const int* __restrict__ row, const int* __restrict__ col) {
    for (int e = blockIdx.x * blockDim.x + threadIdx.x; e < N_EDGES;
         e += gridDim.x * blockDim.x) {
        int r = row[e], c = col[e];
        int pos = atomicAdd(&g_cursor[c], 1);
        g_src[pos] = r;
        g_eperm[pos] = e;
        g_enorm[pos] = rsqrtf(g_deg[r]) * rsqrtf(g_deg[c]);
    }
}

// ---------------- encoders ----------------
__global__ void encode_atoms_kernel(const int* __restrict__ x,
                                    const float* __restrict__ at,
                                    float* __restrict__ total) {
    int n = blockIdx.x * 4 + (threadIdx.x >> 5);
    if (n >= N_NODES) return;
    int d4 = (threadIdx.x & 31) * 4;
    float4 s = make_float4(0.f, 0.f, 0.f, 0.f);
#pragma unroll
    for (int c = 0; c < 9; c++) {
        int idx = __ldg(&x[n * 9 + c]);
        float4 v = *(const float4*)&at[((size_t)c * AVC + idx) * D + d4];
        s.x += v.x; s.y += v.y; s.z += v.z; s.w += v.w;
    }
    *(float4*)&g_h0[(size_t)n * D + d4] = s;
    *(float4*)&total[(size_t)n * D + d4] = s;
}

// bond embeddings written in CSR-permuted order as fp16
__global__ void encode_bonds_kernel(const int* __restrict__ ea,
                                    const float* __restrict__ bt) {
    int pos = blockIdx.x * 4 + (threadIdx.x >> 5);
    if (pos >= N_EDGES) return;
    int e = g_eperm[pos];
    int d4 = (threadIdx.x & 31) * 4;
    float4 s = make_float4(0.f, 0.f, 0.f, 0.f);
#pragma unroll
    for (int c = 0; c < 3; c++) {
        int idx = __ldg(&ea[e * 3 + c]);
        float4 v = *(const float4*)&bt[((size_t)c * BVC + idx) * D + d4];
        s.x += v.x; s.y += v.y; s.z += v.z; s.w += v.w;
    }
    __half2 h01 = __floats2half2_rn(s.x, s.y);
    __half2 h23 = __floats2half2_rn(s.z, s.w);
    uint2 p;
    p.x = *(uint32_t*)&h01;
    p.y = *(uint32_t*)&h23;
    *(uint2*)&g_edgeh[(size_t)pos * D + d4] = p;
}

// ---------------- GEMM (tf32 tensor cores, 3-term split, reg prefetch) ----------------
// bn_mode==0: A = g_h0 raw.
// bn_mode==1: A = relu(bn(g_out)); fused: total += A  (finalize of previous layer,
//             relu always applies since fused layers are 0..L-2).
// Writes only g_hl. Block 0 zeroes g_stats for the following gather.
__global__ __launch_bounds__(256, 2)
void gemm_tc_kernel(int bn_mode,
                    const float* __restrict__ Wl, const float* __restrict__ bias,
                    float* __restrict__ total) {
    __shared__ uint32_t shA[128 * 40];
    __shared__ uint32_t shB[128 * 40];

    const float* A = bn_mode ? g_out : g_h0;

    const int tid = threadIdx.x;
    if (blockIdx.x == 0 && tid < 2 * D) g_stats[tid] = 0.f;

    const int m0 = blockIdx.x * 128;
    const int lane = tid & 31, grp = lane >> 2, tig = lane & 3;
    const int wid = tid >> 5;
    const int wm = (wid & 1) * 64;
    const int wn = (wid >> 1) * 32;

    const int sr0 = tid >> 2,         sc0 = (tid & 3) * 4;
    const int sr1 = (tid + 256) >> 2, sc1 = ((tid + 256) & 3) * 4;

    float acc[4][4][4];
#pragma unroll
    for (int i = 0; i < 4; i++)
#pragma unroll
        for (int j = 0; j < 4; j++)
#pragma unroll
            for (int k = 0; k < 4; k++) acc[i][j][k] = 0.f;

    const float4 z4 = make_float4(0.f, 0.f, 0.f, 0.f);
    float4 ra[2], rb[2];
    {
        int m = m0 + sr0;
        ra[0] = (m < N_NODES) ? *(const float4*)&A[(size_t)m * D + sc0] : z4;
        m = m0 + sr1;
        ra[1] = (m < N_NODES) ? *(const float4*)&A[(size_t)m * D + sc1] : z4;
        rb[0] = *(const float4*)&Wl[sr0 * D + sc0];
        rb[1] = *(const float4*)&Wl[sr1 * D + sc1];
    }

    for (int k0 = 0; k0 < 128; k0 += 16) {
#pragma unroll
        for (int it = 0; it < 2; it++) {
            int r  = it ? sr1 : sr0;
            int c4 = it ? sc1 : sc0;
            float4 v = ra[it];
            if (bn_mode) {
                float4 sc = *(const float4*)&g_bn[k0 + c4];
                float4 sh = *(const float4*)&g_bn[D + k0 + c4];
                v.x = fmaxf(v.x * sc.x + sh.x, 0.f);
                v.y = fmaxf(v.y * sc.y + sh.y, 0.f);
                v.z = fmaxf(v.z * sc.z + sh.z, 0.f);
                v.w = fmaxf(v.w * sc.w + sh.w, 0.f);
                int m = m0 + r;
                if (m < N_NODES) {   // fused finalize of previous layer
                    float* tp = &total[(size_t)m * D + k0 + c4];
                    float4 t = *(float4*)tp;
                    t.x += v.x; t.y += v.y; t.z += v.z; t.w += v.w;
                    *(float4*)tp = t;
                }
            }
            uint32_t* p = &shA[r * 40 + c4 * 2];
            float e[4] = {v.x, v.y, v.z, v.w};
#pragma unroll
            for (int q = 0; q < 4; q++) {
                uint32_t hi = f2tf32(e[q]);
                p[2 * q] = hi;
                p[2 * q + 1] = f2tf32(e[q] - __uint_as_float(hi));
            }
            float4 w = rb[it];
            uint32_t* pb = &shB[r * 40 + c4 * 2];
            float ew[4] = {w.x, w.y, w.z, w.w};
#pragma unroll
            for (int q = 0; q < 4; q++) {
                uint32_t hi = f2tf32(ew[q]);
                pb[2 * q] = hi;
                pb[2 * q + 1] = f2tf32(ew[q] - __uint_as_float(hi));
            }
        }
        __syncthreads();

        if (k0 + 16 < 128) {
            int kn = k0 + 16;
            int m = m0 + sr0;
            ra[0] = (m < N_NODES) ? *(const float4*)&A[(size_t)m * D + kn + sc0] : z4;
            m = m0 + sr1;
            ra[1] = (m < N_NODES) ? *(const float4*)&A[(size_t)m * D + kn + sc1] : z4;
            rb[0] = *(const float4*)&Wl[sr0 * D + kn + sc0];
            rb[1] = *(const float4*)&Wl[sr1 * D + kn + sc1];
        }

#pragma unroll
        for (int ks = 0; ks < 16; ks += 8) {
            uint32_t bh[4][2], bl[4][2];
#pragma unroll
            for (int j = 0; j < 4; j++) {
                int n = wn + j * 8 + grp;
                uint2 p0 = *(const uint2*)&shB[n * 40 + (ks + tig) * 2];
                uint2 p1 = *(const uint2*)&shB[n * 40 + (ks + tig + 4) * 2];
                bh[j][0] = p0.x; bl[j][0] = p0.y;
                bh[j][1] = p1.x; bl[j][1] = p1.y;
            }
#pragma unroll
            for (int i = 0; i < 4; i++) {
                int r0 = wm + i * 16 + grp;
                uint2 q0 = *(const uint2*)&shA[r0 * 40 + (ks + tig) * 2];
                uint2 q1 = *(const uint2*)&shA[(r0 + 8) * 40 + (ks + tig) * 2];
                uint2 q2 = *(const uint2*)&shA[r0 * 40 + (ks + tig + 4) * 2];
                uint2 q3 = *(const uint2*)&shA[(r0 + 8) * 40 + (ks + tig + 4) * 2];
                uint32_t ah[4] = {q0.x, q1.x, q2.x, q3.x};
                uint32_t al[4] = {q0.y, q1.y, q2.y, q3.y};
#pragma unroll
                for (int j = 0; j < 4; j++) {
                    mma_tf32(acc[i][j], ah, bh[j]);
                    mma_tf32(acc[i][j], al, bh[j]);
                    mma_tf32(acc[i][j], ah, bl[j]);
                }
            }
        }
        __syncthreads();
    }

    // epilogue: write hl only
    float bs[4][2];
#pragma unroll
    for (int j = 0; j < 4; j++) {
        int col = wn + j * 8 + tig * 2;
        bs[j][0] = __ldg(&bias[col]);  bs[j][1] = __ldg(&bias[col + 1]);
    }
#pragma unroll
    for (int i = 0; i < 4; i++) {
        int rbase = m0 + wm + i * 16 + grp;
#pragma unroll
        for (int half = 0; half < 2; half++) {
            int m = rbase + half * 8;
            if (m >= N_NODES) continue;
#pragma unroll
            for (int j = 0; j < 4; j++) {
                int col = wn + j * 8 + tig * 2;
                float v0 = acc[i][j][half * 2 + 0] + bs[j][0];
                float v1 = acc[i][j][half * 2 + 1] + bs[j][1];
                *(float2*)&g_hl[(size_t)m * D + col] = make_float2(v0, v1);
            }
        }
    }
}

// ---------------- gather message + self term + fused BN stats ----------------
// out[n] = relu(hl[n]+root)/deg[n] + sum_{k in csr(n)} enorm[k]*relu(hl[src[k]]+edge[k])
__global__ __launch_bounds__(256)
void gather_kernel(const float* __restrict__ root) {
    __shared__ float shs[8 * 128];
    __shared__ float shq[8 * 128];
    int wid = threadIdx.x >> 5, lane = threadIdx.x & 31;
    int d4 = lane * 4;
    float4 rt = *(const float4*)&root[d4];
    float4 sum = make_float4(0.f, 0.f, 0.f, 0.f);
    float4 sq  = make_float4(0.f, 0.f, 0.f, 0.f);

    for (int n = blockIdx.x * 8 + wid; n < N_NODES; n += gridDim.x * 8) {
        int start = g_off[n];
        int end = (n < N_NODES - 1) ? g_off[n + 1] : N_EDGES;
        float inv = 1.f / g_deg[n];
        float4 hn = *(const float4*)&g_hl[(size_t)n * D + d4];
        float4 acc;
        acc.x = fmaxf(hn.x + rt.x, 0.f) * inv;
        acc.y = fmaxf(hn.y + rt.y, 0.f) * inv;
        acc.z = fmaxf(hn.z + rt.z, 0.f) * inv;
        acc.w = fmaxf(hn.w + rt.w, 0.f) * inv;
        for (int k = start; k < end; k++) {
            int s = g_src[k];
            float nm = g_enorm[k];
            float4 h = *(const float4*)&g_hl[(size_t)s * D + d4];
            uint2 ep = *(const uint2*)&g_edgeh[(size_t)k * D + d4];
            float2 e01 = __half22float2(*(__half2*)&ep.x);
            float2 e23 = __half22float2(*(__half2*)&ep.y);
            acc.x += fmaxf(h.x + e01.x, 0.f) * nm;
            acc.y += fmaxf(h.y + e01.y, 0.f) * nm;
            acc.z += fmaxf(h.z + e23.x, 0.f) * nm;
            acc.w += fmaxf(h.w + e23.y, 0.f) * nm;
        }
        *(float4*)&g_out[(size_t)n * D + d4] = acc;
        sum.x += acc.x; sum.y += acc.y; sum.z += acc.z; sum.w += acc.w;
        sq.x += acc.x * acc.x; sq.y += acc.y * acc.y;
        sq.z += acc.z * acc.z; sq.w += acc.w * acc.w;
    }

    *(float4*)&shs[wid * 128 + d4] = sum;
    *(float4*)&shq[wid * 128 + d4] = sq;
    __syncthreads();
    if (threadIdx.x < 128) {
        float s = 0.f, q = 0.f;
#pragma unroll
        for (int w = 0; w < 8; w++) {
            s += shs[w * 128 + threadIdx.x];
            q += shq[w * 128 + threadIdx.x];
        }
        atomicAdd(&g_stats[threadIdx.x], s);
        atomicAdd(&g_stats[D + threadIdx.x], q);
    }
}

// ---------------- batch-norm params / last-layer finalize ----------------
__global__ void bn_kernel(const float* __restrict__ gamma, const float* __restrict__ beta) {
    int d = threadIdx.x;
    float mean = g_stats[d] * (1.f / N_NODES);
    float var = g_stats[D + d] * (1.f / N_NODES) - mean * mean;
    float sc = __ldg(&gamma[d]) * rsqrtf(var + BN_EPS);
    g_bn[d] = sc;
    g_bn[D + d] = __ldg(&beta[d]) - mean * sc;
}

__global__ void finalize_kernel(float* __restrict__ total) {   // last layer: no relu
    int lane = threadIdx.x & 31;
    int warp = threadIdx.x >> 5;
    int d4 = lane * 4;
    float4 sc = *(const float4*)&g_bn[d4];
    float4 sh = *(const float4*)&g_bn[D + d4];
    for (int n = blockIdx.x * 8 + warp; n < N_NODES; n += gridDim.x * 8) {
        size_t idx = (size_t)n * D + d4;
        float4 v = *(const float4*)&g_out[idx];
        float4 t = *(const float4*)&total[idx];
        t.x += v.x * sc.x + sh.x;
        t.y += v.y * sc.y + sh.y;
        t.z += v.z * sc.z + sh.z;
        t.w += v.w * sc.w + sh.w;
        *(float4*)&total[idx] = t;
    }
}

// ---------------- launch ----------------
extern "C" void kernel_launch(void* const* d_in, const int* in_sizes, int n_in,
                              void* d_out, int out_size) {
    const int* x     = (const int*)d_in[0];
    const int* ei    = (const int*)d_in[1];
    const int* row   = ei;            // edge_index[0] : source j
    const int* col   = ei + N_EDGES;  // edge_index[1] : target i
    const int* ea    = (const int*)d_in[2];
    const float* at  = (const float*)d_in[3];
    const float* bt  = (const float*)d_in[4];
    const float* W   = (const float*)d_in[5];
    const float* b   = (const float*)d_in[6];
    const float* root  = (const float*)d_in[7];
    const float* gamma = (const float*)d_in[8];
    const float* beta  = (const float*)d_in[9];
    float* total = (float*)d_out;

    const int nscan = (N_NODES + 255) / 256;   // 782

    init_kernel<<<1024, 256>>>();
    deg_acc_kernel<<<1024, 256>>>(row);
    indeg_acc_kernel<<<1024, 256>>>(col);
    scan1_kernel<<<nscan, 256>>>();
    scan2_kernel<<<1, 1024>>>(nscan);
    scan3_kernel<<<nscan, 256>>>();
    fill_kernel<<<1024, 256>>>(row, col);
    encode_atoms_kernel<<<(N_NODES + 3) / 4, 128>>>(x, at, total);
    encode_bonds_kernel<<<(N_EDGES + 3) / 4, 128>>>(ea, bt);

    for (int l = 0; l < NLAYER; l++) {
        gemm_tc_kernel<<<(N_NODES + 127) / 128, 256>>>(
            l == 0 ? 0 : 1,
            W + (size_t)l * D * D, b + (size_t)l * D, total);
        gather_kernel<<<2048, 256>>>(root + (size_t)l * D);
        bn_kernel<<<1, 128>>>(gamma + (size_t)l * D, beta + (size_t)l * D);
    }
    finalize_kernel<<<2048, 256>>>(total);
}

// round 7
// speedup vs baseline: 2.8023x; 1.0958x over previous
#include <cuda_runtime.h>
#include <cuda_fp16.h>
#include <cstdint>

#define N_NODES 200000
#define N_EDGES 400000
#define D 128
#define NLAYER 5
#define AVC 100
#define BVC 10
#define BN_EPS 1e-5f

// ---------------- scratch (static device globals; no allocation) ----------------
__device__ __half g_hlh[(size_t)N_NODES * D];   // linear output (fp16; gather-only consumer)
__device__ float g_out[(size_t)N_NODES * D];    // aggregated output (pre-BN) / h carrier
__device__ float g_h0[(size_t)N_NODES * D];     // encoder output (layer-0 input)
__device__ __half g_edgeh[(size_t)N_EDGES * D]; // bond embeddings (CSR-permuted, fp16)
__device__ float g_deg[N_NODES];
__device__ float g_enorm[N_EDGES];              // norm per CSR slot
__device__ int   g_indeg[N_NODES];
__device__ int   g_off[N_NODES];                // CSR offsets (exclusive scan)
__device__ int   g_cursor[N_NODES];
__device__ int   g_bsum[1024];
__device__ int   g_src[N_EDGES];                // source node per CSR slot
__device__ int   g_eperm[N_EDGES];              // original edge id per CSR slot
__device__ float g_stats[2 * D];                // sum, sumsq
__device__ float g_bn[2 * D];                   // scale, shift

// ---------------- helpers ----------------
__device__ __forceinline__ uint32_t f2tf32(float f) {
    uint32_t r;
    asm("cvt.rna.tf32.f32 %0, %1;" : "=r"(r) : "f"(f));
    return r;
}

__device__ __forceinline__ void mma_tf32(float* d, const uint32_t* a, const uint32_t* b) {
    asm volatile(
        "mma.sync.aligned.m16n8k8.row.col.f32.tf32.tf32.f32 "
        "{%0,%1,%2,%3}, {%4,%5,%6,%7}, {%8,%9}, {%0,%1,%2,%3};\n"
        : "+f"(d[0]), "+f"(d[1]), "+f"(d[2]), "+f"(d[3])
        : "r"(a[0]), "r"(a[1]), "r"(a[2]), "r"(a[3]), "r"(b[0]), "r"(b[1]));
}

// ---------------- setup: degrees + CSR ----------------
__global__ void init_kernel() {
    int stride = gridDim.x * blockDim.x;
    for (int i = blockIdx.x * blockDim.x + threadIdx.x; i < N_NODES; i += stride) {
        g_deg[i] = 1.f;
        g_indeg[i] = 0;
    }
}

__global__ void deg_acc_kernel(const int* __restrict__ row) {
    for (int e = blockIdx.x * blockDim.x + threadIdx.x; e < N_EDGES;
         e += gridDim.x * blockDim.x)
        atomicAdd(&g_deg[row[e]], 1.f);
}

__global__ void indeg_acc_kernel(const int* __restrict__ col) {
    for (int e = blockIdx.x * blockDim.x + threadIdx.x; e < N_EDGES;
         e += gridDim.x * blockDim.x)
        atomicAdd(&g_indeg[col[e]], 1);
}

__global__ void scan1_kernel() {
    __shared__ int sh[256];
    int tid = threadIdx.x;
    int i = blockIdx.x * 256 + tid;
    int v = (i < N_NODES) ? g_indeg[i] : 0;
    sh[tid] = v;
    __syncthreads();
#pragma unroll
    for (int ofs = 1; ofs < 256; ofs <<= 1) {
        int t = (tid >= ofs) ? sh[tid - ofs] : 0;
        __syncthreads();
        sh[tid] += t;
        __syncthreads();
    }
    if (i < N_NODES) g_off[i] = sh[tid] - v;  // exclusive
    if (tid == 255) g_bsum[blockIdx.x] = sh[255];
}

__global__ void scan2_kernel(int nblk) {   // single block of 1024
    __shared__ int sh[1024];
    int tid = threadIdx.x;
    int v = (tid < nblk) ? g_bsum[tid] : 0;
    sh[tid] = v;
    __syncthreads();
#pragma unroll
    for (int ofs = 1; ofs < 1024; ofs <<= 1) {
        int t = (tid >= ofs) ? sh[tid - ofs] : 0;
        __syncthreads();
        sh[tid] += t;
        __syncthreads();
    }
    if (tid < nblk) g_bsum[tid] = sh[tid] - v;  // exclusive
}

__global__ void scan3_kernel() {
    int i = blockIdx.x * 256 + threadIdx.x;
    if (i < N_NODES) {
        int o = g_off[i] + g_bsum[blockIdx.x];
        g_off[i] = o;
        g_cursor[i] = o;
    }
}

__global__ void fill_kernel(const int* __restrict__ row, const int* __restrict__ col) {
    for (int e = blockIdx.x * blockDim.x + threadIdx.x; e < N_EDGES;
         e += gridDim.x * blockDim.x) {
        int r = row[e], c = col[e];
        int pos = atomicAdd(&g_cursor[c], 1);
        g_src[pos] = r;
        g_eperm[pos] = e;
        g_enorm[pos] = rsqrtf(g_deg[r]) * rsqrtf(g_deg[c]);
    }
}

// ---------------- encoders ----------------
__global__ void encode_atoms_kernel(const int* __restrict__ x,
                                    const float* __restrict__ at,
                                    float* __restrict__ total) {
    int n = blockIdx.x * 4 + (threadIdx.x >> 5);
    if (n >= N_NODES) return;
    int d4 = (threadIdx.x & 31) * 4;
    float4 s = make_float4(0.f, 0.f, 0.f, 0.f);
#pragma unroll
    for (int c = 0; c < 9; c++) {
        int idx = __ldg(&x[n * 9 + c]);
        float4 v = *(const float4*)&at[((size_t)c * AVC + idx) * D + d4];
        s.x += v.x; s.y += v.y; s.z += v.z; s.w += v.w;
    }
    *(float4*)&g_h0[(size_t)n * D + d4] = s;
    *(float4*)&total[(size_t)n * D + d4] = s;
}

// bond embeddings written in CSR-permuted order as fp16
__global__ void encode_bonds_kernel(const int* __restrict__ ea,
                                    const float* __restrict__ bt) {
    int pos = blockIdx.x * 4 + (threadIdx.x >> 5);
    if (pos >= N_EDGES) return;
    int e = g_eperm[pos];
    int d4 = (threadIdx.x & 31) * 4;
    float4 s = make_float4(0.f, 0.f, 0.f, 0.f);
#pragma unroll
    for (int c = 0; c < 3; c++) {
        int idx = __ldg(&ea[e * 3 + c]);
        float4 v = *(const float4*)&bt[((size_t)c * BVC + idx) * D + d4];
        s.x += v.x; s.y += v.y; s.z += v.z; s.w += v.w;
    }
    __half2 h01 = __floats2half2_rn(s.x, s.y);
    __half2 h23 = __floats2half2_rn(s.z, s.w);
    uint2 p;
    p.x = *(uint32_t*)&h01;
    p.y = *(uint32_t*)&h23;
    *(uint2*)&g_edgeh[(size_t)pos * D + d4] = p;
}

// ---------------- GEMM (tf32 tensor cores, 3-term split, reg prefetch) ----------------
// bn_mode==0: A = g_h0 raw.
// bn_mode==1: A = relu(bn(g_out)); fused: total += A  (finalize of previous layer).
// Writes g_hlh (fp16). Block 0 zeroes g_stats for the following gather.
__global__ __launch_bounds__(256, 2)
void gemm_tc_kernel(int bn_mode,
                    const float* __restrict__ Wl, const float* __restrict__ bias,
                    float* __restrict__ total) {
    __shared__ uint32_t shA[128 * 40];
    __shared__ uint32_t shB[128 * 40];

    const float* A = bn_mode ? g_out : g_h0;

    const int tid = threadIdx.x;
    if (blockIdx.x == 0 && tid < 2 * D) g_stats[tid] = 0.f;

    const int m0 = blockIdx.x * 128;
    const int lane = tid & 31, grp = lane >> 2, tig = lane & 3;
    const int wid = tid >> 5;
    const int wm = (wid & 1) * 64;
    const int wn = (wid >> 1) * 32;

    const int sr0 = tid >> 2,         sc0 = (tid & 3) * 4;
    const int sr1 = (tid + 256) >> 2, sc1 = ((tid + 256) & 3) * 4;

    float acc[4][4][4];
#pragma unroll
    for (int i = 0; i < 4; i++)
#pragma unroll
        for (int j = 0; j < 4; j++)
#pragma unroll
            for (int k = 0; k < 4; k++) acc[i][j][k] = 0.f;

    const float4 z4 = make_float4(0.f, 0.f, 0.f, 0.f);
    float4 ra[2], rb[2];
    {
        int m = m0 + sr0;
        ra[0] = (m < N_NODES) ? *(const float4*)&A[(size_t)m * D + sc0] : z4;
        m = m0 + sr1;
        ra[1] = (m < N_NODES) ? *(const float4*)&A[(size_t)m * D + sc1] : z4;
        rb[0] = *(const float4*)&Wl[sr0 * D + sc0];
        rb[1] = *(const float4*)&Wl[sr1 * D + sc1];
    }

    for (int k0 = 0; k0 < 128; k0 += 16) {
#pragma unroll
        for (int it = 0; it < 2; it++) {
            int r  = it ? sr1 : sr0;
            int c4 = it ? sc1 : sc0;
            float4 v = ra[it];
            if (bn_mode) {
                float4 sc = *(const float4*)&g_bn[k0 + c4];
                float4 sh = *(const float4*)&g_bn[D + k0 + c4];
                v.x = fmaxf(v.x * sc.x + sh.x, 0.f);
                v.y = fmaxf(v.y * sc.y + sh.y, 0.f);
                v.z = fmaxf(v.z * sc.z + sh.z, 0.f);
                v.w = fmaxf(v.w * sc.w + sh.w, 0.f);
                int m = m0 + r;
                if (m < N_NODES) {   // fused finalize of previous layer
                    float* tp = &total[(size_t)m * D + k0 + c4];
                    float4 t = *(float4*)tp;
                    t.x += v.x; t.y += v.y; t.z += v.z; t.w += v.w;
                    *(float4*)tp = t;
                }
            }
            uint32_t* p = &shA[r * 40 + c4 * 2];
            float e[4] = {v.x, v.y, v.z, v.w};
#pragma unroll
            for (int q = 0; q < 4; q++) {
                uint32_t hi = f2tf32(e[q]);
                p[2 * q] = hi;
                p[2 * q + 1] = f2tf32(e[q] - __uint_as_float(hi));
            }
            float4 w = rb[it];
            uint32_t* pb = &shB[r * 40 + c4 * 2];
            float ew[4] = {w.x, w.y, w.z, w.w};
#pragma unroll
            for (int q = 0; q < 4; q++) {
                uint32_t hi = f2tf32(ew[q]);
                pb[2 * q] = hi;
                pb[2 * q + 1] = f2tf32(ew[q] - __uint_as_float(hi));
            }
        }
        __syncthreads();

        if (k0 + 16 < 128) {
            int kn = k0 + 16;
            int m = m0 + sr0;
            ra[0] = (m < N_NODES) ? *(const float4*)&A[(size_t)m * D + kn + sc0] : z4;
            m = m0 + sr1;
            ra[1] = (m < N_NODES) ? *(const float4*)&A[(size_t)m * D + kn + sc1] : z4;
            rb[0] = *(const float4*)&Wl[sr0 * D + kn + sc0];
            rb[1] = *(const float4*)&Wl[sr1 * D + kn + sc1];
        }

#pragma unroll
        for (int ks = 0; ks < 16; ks += 8) {
            uint32_t bh[4][2], bl[4][2];
#pragma unroll
            for (int j = 0; j < 4; j++) {
                int n = wn + j * 8 + grp;
                uint2 p0 = *(const uint2*)&shB[n * 40 + (ks + tig) * 2];
                uint2 p1 = *(const uint2*)&shB[n * 40 + (ks + tig + 4) * 2];
                bh[j][0] = p0.x; bl[j][0] = p0.y;
                bh[j][1] = p1.x; bl[j][1] = p1.y;
            }
#pragma unroll
            for (int i = 0; i < 4; i++) {
                int r0 = wm + i * 16 + grp;
                uint2 q0 = *(const uint2*)&shA[r0 * 40 + (ks + tig) * 2];
                uint2 q1 = *(const uint2*)&shA[(r0 + 8) * 40 + (ks + tig) * 2];
                uint2 q2 = *(const uint2*)&shA[r0 * 40 + (ks + tig + 4) * 2];
                uint2 q3 = *(const uint2*)&shA[(r0 + 8) * 40 + (ks + tig + 4) * 2];
                uint32_t ah[4] = {q0.x, q1.x, q2.x, q3.x};
                uint32_t al[4] = {q0.y, q1.y, q2.y, q3.y};
#pragma unroll
                for (int j = 0; j < 4; j++) {
                    mma_tf32(acc[i][j], ah, bh[j]);
                    mma_tf32(acc[i][j], al, bh[j]);
                    mma_tf32(acc[i][j], ah, bl[j]);
                }
            }
        }
        __syncthreads();
    }

    // epilogue: write hl as fp16 (half2 per accumulator pair)
    float bs[4][2];
#pragma unroll
    for (int j = 0; j < 4; j++) {
        int col = wn + j * 8 + tig * 2;
        bs[j][0] = __ldg(&bias[col]);  bs[j][1] = __ldg(&bias[col + 1]);
    }
#pragma unroll
    for (int i = 0; i < 4; i++) {
        int rbase = m0 + wm + i * 16 + grp;
#pragma unroll
        for (int half = 0; half < 2; half++) {
            int m = rbase + half * 8;
            if (m >= N_NODES) continue;
#pragma unroll
            for (int j = 0; j < 4; j++) {
                int col = wn + j * 8 + tig * 2;
                float v0 = acc[i][j][half * 2 + 0] + bs[j][0];
                float v1 = acc[i][j][half * 2 + 1] + bs[j][1];
                __half2 h = __floats2half2_rn(v0, v1);
                *(uint32_t*)&g_hlh[(size_t)m * D + col] = *(uint32_t*)&h;
            }
        }
    }
}

// ---------------- gather message + self term + fused BN stats ----------------
// out[n] = relu(hl[n]+root)/deg[n] + sum_{k in csr(n)} enorm[k]*relu(hl[src[k]]+edge[k])
__global__ __launch_bounds__(256)
void gather_kernel(const float* __restrict__ root) {
    __shared__ float shs[8 * 128];
    __shared__ float shq[8 * 128];
    int wid = threadIdx.x >> 5, lane = threadIdx.x & 31;
    int d4 = lane * 4;
    float4 rt = *(const float4*)&root[d4];
    float4 sum = make_float4(0.f, 0.f, 0.f, 0.f);
    float4 sq  = make_float4(0.f, 0.f, 0.f, 0.f);

    for (int n = blockIdx.x * 8 + wid; n < N_NODES; n += gridDim.x * 8) {
        int start = g_off[n];
        int end = (n < N_NODES - 1) ? g_off[n + 1] : N_EDGES;
        float inv = 1.f / g_deg[n];
        uint2 hp = *(const uint2*)&g_hlh[(size_t)n * D + d4];
        float2 h01 = __half22float2(*(__half2*)&hp.x);
        float2 h23 = __half22float2(*(__half2*)&hp.y);
        float4 acc;
        acc.x = fmaxf(h01.x + rt.x, 0.f) * inv;
        acc.y = fmaxf(h01.y + rt.y, 0.f) * inv;
        acc.z = fmaxf(h23.x + rt.z, 0.f) * inv;
        acc.w = fmaxf(h23.y + rt.w, 0.f) * inv;
        for (int k = start; k < end; k++) {
            int s = g_src[k];
            float nm = g_enorm[k];
            uint2 sp = *(const uint2*)&g_hlh[(size_t)s * D + d4];
            float2 s01 = __half22float2(*(__half2*)&sp.x);
            float2 s23 = __half22float2(*(__half2*)&sp.y);
            uint2 ep = *(const uint2*)&g_edgeh[(size_t)k * D + d4];
            float2 e01 = __half22float2(*(__half2*)&ep.x);
            float2 e23 = __half22float2(*(__half2*)&ep.y);
            acc.x += fmaxf(s01.x + e01.x, 0.f) * nm;
            acc.y += fmaxf(s01.y + e01.y, 0.f) * nm;
            acc.z += fmaxf(s23.x + e23.x, 0.f) * nm;
            acc.w += fmaxf(s23.y + e23.y, 0.f) * nm;
        }
        *(float4*)&g_out[(size_t)n * D + d4] = acc;
        sum.x += acc.x; sum.y += acc.y; sum.z += acc.z; sum.w += acc.w;
        sq.x += acc.x * acc.x; sq.y += acc.y * acc.y;
        sq.z += acc.z * acc.z; sq.w += acc.w * acc.w;
    }

    *(float4*)&shs[wid * 128 + d4] = sum;
    *(float4*)&shq[wid * 128 + d4] = sq;
    __syncthreads();
    if (threadIdx.x < 128) {
        float s = 0.f, q = 0.f;
#pragma unroll
        for (int w = 0; w < 8; w++) {
            s += shs[w * 128 + threadIdx.x];
            q += shq[w * 128 + threadIdx.x];
        }
        atomicAdd(&g_stats[threadIdx.x], s);
        atomicAdd(&g_stats[D + threadIdx.x], q);
    }
}

// ---------------- batch-norm params / last-layer finalize ----------------
__global__ void bn_kernel(const float* __restrict__ gamma, const float* __restrict__ beta) {
    int d = threadIdx.x;
    float mean = g_stats[d] * (1.f / N_NODES);
    float var = g_stats[D + d] * (1.f / N_NODES) - mean * mean;
    float sc = __ldg(&gamma[d]) * rsqrtf(var + BN_EPS);
    g_bn[d] = sc;
    g_bn[D + d] = __ldg(&beta[d]) - mean * sc;
}

__global__ void finalize_kernel(float* __restrict__ total) {   // last layer: no relu
    int lane = threadIdx.x & 31;
    int warp = threadIdx.x >> 5;
    int d4 = lane * 4;
    float4 sc = *(const float4*)&g_bn[d4];
    float4 sh = *(const float4*)&g_bn[D + d4];
    for (int n = blockIdx.x * 8 + warp; n < N_NODES; n += gridDim.x * 8) {
        size_t idx = (size_t)n * D + d4;
        float4 v = *(const float4*)&g_out[idx];
        float4 t = *(const float4*)&total[idx];
        t.x += v.x * sc.x + sh.x;
        t.y += v.y * sc.y + sh.y;
        t.z += v.z * sc.z + sh.z;
        t.w += v.w * sc.w + sh.w;
        *(float4*)&total[idx] = t;
    }
}

// ---------------- launch ----------------
extern "C" void kernel_launch(void* const* d_in, const int* in_sizes, int n_in,
                              void* d_out, int out_size) {
    const int* x     = (const int*)d_in[0];
    const int* ei    = (const int*)d_in[1];
    const int* row   = ei;            // edge_index[0] : source j
    const int* col   = ei + N_EDGES;  // edge_index[1] : target i
    const int* ea    = (const int*)d_in[2];
    const float* at  = (const float*)d_in[3];
    const float* bt  = (const float*)d_in[4];
    const float* W   = (const float*)d_in[5];
    const float* b   = (const float*)d_in[6];
    const float* root  = (const float*)d_in[7];
    const float* gamma = (const float*)d_in[8];
    const float* beta  = (const float*)d_in[9];
    float* total = (float*)d_out;

    const int nscan = (N_NODES + 255) / 256;   // 782

    init_kernel<<<1024, 256>>>();
    deg_acc_kernel<<<1024, 256>>>(row);
    indeg_acc_kernel<<<1024, 256>>>(col);
    scan1_kernel<<<nscan, 256>>>();
    scan2_kernel<<<1, 1024>>>(nscan);
    scan3_kernel<<<nscan, 256>>>();
    fill_kernel<<<1024, 256>>>(row, col);
    encode_atoms_kernel<<<(N_NODES + 3) / 4, 128>>>(x, at, total);
    encode_bonds_kernel<<<(N_EDGES + 3) / 4, 128>>>(ea, bt);

    for (int l = 0; l < NLAYER; l++) {
        gemm_tc_kernel<<<(N_NODES + 127) / 128, 256>>>(
            l == 0 ? 0 : 1,
            W + (size_t)l * D * D, b + (size_t)l * D, total);
        gather_kernel<<<2048, 256>>>(root + (size_t)l * D);
        bn_kernel<<<1, 128>>>(gamma + (size_t)l * D, beta + (size_t)l * D);
    }
    finalize_kernel<<<2048, 256>>>(total);
}

// round 8
// speedup vs baseline: 2.8978x; 1.0341x over previous
#include <cuda_runtime.h>
#include <cuda_fp16.h>
#include <cstdint>

#define N_NODES 200000
#define N_EDGES 400000
#define D 128
#define NLAYER 5
#define AVC 100
#define BVC 10
#define BN_EPS 1e-5f
#define ND ((size_t)N_NODES * D)

// ---------------- scratch (static device globals; no allocation) ----------------
__device__ __half g_hlh[ND];                    // linear output (fp16; gather-only consumer)
__device__ float g_outL[NLAYER * ND];           // per-layer aggregated output (pre-BN)
__device__ float g_h0[ND];                      // encoder output (layer-0 input)
__device__ __half g_edgeh[(size_t)N_EDGES * D]; // bond embeddings (CSR-permuted, fp16)
__device__ float g_deg[N_NODES];
__device__ float g_enorm[N_EDGES];              // norm per CSR slot
__device__ int   g_indeg[N_NODES];
__device__ int   g_off[N_NODES];                // CSR offsets (exclusive scan)
__device__ int   g_cursor[N_NODES];
__device__ int   g_bsum[1024];
__device__ int   g_src[N_EDGES];                // source node per CSR slot
__device__ int   g_eperm[N_EDGES];              // original edge id per CSR slot
__device__ float g_stats[2 * D];                // sum, sumsq
__device__ float g_bnL[NLAYER * 2 * D];         // per-layer scale, shift

// ---------------- helpers ----------------
__device__ __forceinline__ uint32_t f2tf32(float f) {
    uint32_t r;
    asm("cvt.rna.tf32.f32 %0, %1;" : "=r"(r) : "f"(f));
    return r;
}

__device__ __forceinline__ void mma_tf32(float* d, const uint32_t* a, const uint32_t* b) {
    asm volatile(
        "mma.sync.aligned.m16n8k8.row.col.f32.tf32.tf32.f32 "
        "{%0,%1,%2,%3}, {%4,%5,%6,%7}, {%8,%9}, {%0,%1,%2,%3};\n"
        : "+f"(d[0]), "+f"(d[1]), "+f"(d[2]), "+f"(d[3])
        : "r"(a[0]), "r"(a[1]), "r"(a[2]), "r"(a[3]), "r"(b[0]), "r"(b[1]));
}

// ---------------- setup: degrees + CSR ----------------
__global__ void init_kernel() {
    int stride = gridDim.x * blockDim.x;
    for (int i = blockIdx.x * blockDim.x + threadIdx.x; i < N_NODES; i += stride) {
        g_deg[i] = 1.f;
        g_indeg[i] = 0;
    }
}

__global__ void deg_acc_kernel(const int* __restrict__ row) {
    for (int e = blockIdx.x * blockDim.x + threadIdx.x; e < N_EDGES;
         e += gridDim.x * blockDim.x)
        atomicAdd(&g_deg[row[e]], 1.f);
}

__global__ void indeg_acc_kernel(const int* __restrict__ col) {
    for (int e = blockIdx.x * blockDim.x + threadIdx.x; e < N_EDGES;
         e += gridDim.x * blockDim.x)
        atomicAdd(&g_indeg[col[e]], 1);
}

__global__ void scan1_kernel() {
    __shared__ int sh[256];
    int tid = threadIdx.x;
    int i = blockIdx.x * 256 + tid;
    int v = (i < N_NODES) ? g_indeg[i] : 0;
    sh[tid] = v;
    __syncthreads();
#pragma unroll
    for (int ofs = 1; ofs < 256; ofs <<= 1) {
        int t = (tid >= ofs) ? sh[tid - ofs] : 0;
        __syncthreads();
        sh[tid] += t;
        __syncthreads();
    }
    if (i < N_NODES) g_off[i] = sh[tid] - v;  // exclusive
    if (tid == 255) g_bsum[blockIdx.x] = sh[255];
}

__global__ void scan2_kernel(int nblk) {   // single block of 1024
    __shared__ int sh[1024];
    int tid = threadIdx.x;
    int v = (tid < nblk) ? g_bsum[tid] : 0;
    sh[tid] = v;
    __syncthreads();
#pragma unroll
    for (int ofs = 1; ofs < 1024; ofs <<= 1) {
        int t = (tid >= ofs) ? sh[tid - ofs] : 0;
        __syncthreads();
        sh[tid] += t;
        __syncthreads();
    }
    if (tid < nblk) g_bsum[tid] = sh[tid] - v;  // exclusive
}

__global__ void scan3_kernel() {
    int i = blockIdx.x * 256 + threadIdx.x;
    if (i < N_NODES) {
        int o = g_off[i] + g_bsum[blockIdx.x];
        g_off[i] = o;
        g_cursor[i] = o;
    }
}

__global__ void fill_kernel(const int* __restrict__ row, const int* __restrict__ col) {
    for (int e = blockIdx.x * blockDim.x + threadIdx.x; e < N_EDGES;
         e += gridDim.x * blockDim.x) {
        int r = row[e], c = col[e];
        int pos = atomicAdd(&g_cursor[c], 1);
        g_src[pos] = r;
        g_eperm[pos] = e;
        g_enorm[pos] = rsqrtf(g_deg[r]) * rsqrtf(g_deg[c]);
    }
}

// ---------------- encoders ----------------
__global__ void encode_atoms_kernel(const int* __restrict__ x,
                                    const float* __restrict__ at,
                                    float* __restrict__ total) {
    int n = blockIdx.x * 4 + (threadIdx.x >> 5);
    if (n >= N_NODES) return;
    int d4 = (threadIdx.x & 31) * 4;
    float4 s = make_float4(0.f, 0.f, 0.f, 0.f);
#pragma unroll
    for (int c = 0; c < 9; c++) {
        int idx = __ldg(&x[n * 9 + c]);
        float4 v = *(const float4*)&at[((size_t)c * AVC + idx) * D + d4];
        s.x += v.x; s.y += v.y; s.z += v.z; s.w += v.w;
    }
    *(float4*)&g_h0[(size_t)n * D + d4] = s;
    *(float4*)&total[(size_t)n * D + d4] = s;
}

// bond embeddings written in CSR-permuted order as fp16
__global__ void encode_bonds_kernel(const int* __restrict__ ea,
                                    const float* __restrict__ bt) {
    int pos = blockIdx.x * 4 + (threadIdx.x >> 5);
    if (pos >= N_EDGES) return;
    int e = g_eperm[pos];
    int d4 = (threadIdx.x & 31) * 4;
    float4 s = make_float4(0.f, 0.f, 0.f, 0.f);
#pragma unroll
    for (int c = 0; c < 3; c++) {
        int idx = __ldg(&ea[e * 3 + c]);
        float4 v = *(const float4*)&bt[((size_t)c * BVC + idx) * D + d4];
        s.x += v.x; s.y += v.y; s.z += v.z; s.w += v.w;
    }
    __half2 h01 = __floats2half2_rn(s.x, s.y);
    __half2 h23 = __floats2half2_rn(s.z, s.w);
    uint2 p;
    p.x = *(uint32_t*)&h01;
    p.y = *(uint32_t*)&h23;
    *(uint2*)&g_edgeh[(size_t)pos * D + d4] = p;
}

// ---------------- GEMM (tf32 tensor cores, 3-term split, reg prefetch) ----------------
// layer==0: A = g_h0 raw. layer>0: A = relu(bn(g_outL[layer-1])) on load.
// Writes g_hlh (fp16). Block 0 zeroes g_stats for the following gather.
__global__ __launch_bounds__(256, 2)
void gemm_tc_kernel(int layer,
                    const float* __restrict__ Wl, const float* __restrict__ bias) {
    __shared__ uint32_t shA[128 * 40];
    __shared__ uint32_t shB[128 * 40];

    const float* A = (layer == 0) ? g_h0 : (g_outL + (size_t)(layer - 1) * ND);
    const float* bn = g_bnL + (size_t)(layer > 0 ? layer - 1 : 0) * 2 * D;
    const int bn_mode = (layer > 0);

    const int tid = threadIdx.x;
    if (blockIdx.x == 0 && tid < 2 * D) g_stats[tid] = 0.f;

    const int m0 = blockIdx.x * 128;
    const int lane = tid & 31, grp = lane >> 2, tig = lane & 3;
    const int wid = tid >> 5;
    const int wm = (wid & 1) * 64;
    const int wn = (wid >> 1) * 32;

    const int sr0 = tid >> 2,         sc0 = (tid & 3) * 4;
    const int sr1 = (tid + 256) >> 2, sc1 = ((tid + 256) & 3) * 4;

    float acc[4][4][4];
#pragma unroll
    for (int i = 0; i < 4; i++)
#pragma unroll
        for (int j = 0; j < 4; j++)
#pragma unroll
            for (int k = 0; k < 4; k++) acc[i][j][k] = 0.f;

    const float4 z4 = make_float4(0.f, 0.f, 0.f, 0.f);
    float4 ra[2], rb[2];
    {
        int m = m0 + sr0;
        ra[0] = (m < N_NODES) ? *(const float4*)&A[(size_t)m * D + sc0] : z4;
        m = m0 + sr1;
        ra[1] = (m < N_NODES) ? *(const float4*)&A[(size_t)m * D + sc1] : z4;
        rb[0] = *(const float4*)&Wl[sr0 * D + sc0];
        rb[1] = *(const float4*)&Wl[sr1 * D + sc1];
    }

    for (int k0 = 0; k0 < 128; k0 += 16) {
#pragma unroll
        for (int it = 0; it < 2; it++) {
            int r  = it ? sr1 : sr0;
            int c4 = it ? sc1 : sc0;
            float4 v = ra[it];
            if (bn_mode) {
                float4 sc = *(const float4*)&bn[k0 + c4];
                float4 sh = *(const float4*)&bn[D + k0 + c4];
                v.x = fmaxf(v.x * sc.x + sh.x, 0.f);
                v.y = fmaxf(v.y * sc.y + sh.y, 0.f);
                v.z = fmaxf(v.z * sc.z + sh.z, 0.f);
                v.w = fmaxf(v.w * sc.w + sh.w, 0.f);
            }
            uint32_t* p = &shA[r * 40 + c4 * 2];
            float e[4] = {v.x, v.y, v.z, v.w};
#pragma unroll
            for (int q = 0; q < 4; q++) {
                uint32_t hi = f2tf32(e[q]);
                p[2 * q] = hi;
                p[2 * q + 1] = f2tf32(e[q] - __uint_as_float(hi));
            }
            float4 w = rb[it];
            uint32_t* pb = &shB[r * 40 + c4 * 2];
            float ew[4] = {w.x, w.y, w.z, w.w};
#pragma unroll
            for (int q = 0; q < 4; q++) {
                uint32_t hi = f2tf32(ew[q]);
                pb[2 * q] = hi;
                pb[2 * q + 1] = f2tf32(ew[q] - __uint_as_float(hi));
            }
        }
        __syncthreads();

        if (k0 + 16 < 128) {
            int kn = k0 + 16;
            int m = m0 + sr0;
            ra[0] = (m < N_NODES) ? *(const float4*)&A[(size_t)m * D + kn + sc0] : z4;
            m = m0 + sr1;
            ra[1] = (m < N_NODES) ? *(const float4*)&A[(size_t)m * D + kn + sc1] : z4;
            rb[0] = *(const float4*)&Wl[sr0 * D + kn + sc0];
            rb[1] = *(const float4*)&Wl[sr1 * D + kn + sc1];
        }

#pragma unroll
        for (int ks = 0; ks < 16; ks += 8) {
            uint32_t bh[4][2], bl[4][2];
#pragma unroll
            for (int j = 0; j < 4; j++) {
                int n = wn + j * 8 + grp;
                uint2 p0 = *(const uint2*)&shB[n * 40 + (ks + tig) * 2];
                uint2 p1 = *(const uint2*)&shB[n * 40 + (ks + tig + 4) * 2];
                bh[j][0] = p0.x; bl[j][0] = p0.y;
                bh[j][1] = p1.x; bl[j][1] = p1.y;
            }
#pragma unroll
            for (int i = 0; i < 4; i++) {
                int r0 = wm + i * 16 + grp;
                uint2 q0 = *(const uint2*)&shA[r0 * 40 + (ks + tig) * 2];
                uint2 q1 = *(const uint2*)&shA[(r0 + 8) * 40 + (ks + tig) * 2];
                uint2 q2 = *(const uint2*)&shA[r0 * 40 + (ks + tig + 4) * 2];
                uint2 q3 = *(const uint2*)&shA[(r0 + 8) * 40 + (ks + tig + 4) * 2];
                uint32_t ah[4] = {q0.x, q1.x, q2.x, q3.x};
                uint32_t al[4] = {q0.y, q1.y, q2.y, q3.y};
#pragma unroll
                for (int j = 0; j < 4; j++) {
                    mma_tf32(acc[i][j], ah, bh[j]);
                    mma_tf32(acc[i][j], al, bh[j]);
                    mma_tf32(acc[i][j], ah, bl[j]);
                }
            }
        }
        __syncthreads();
    }

    // epilogue: write hl as fp16 (half2 per accumulator pair)
    float bs[4][2];
#pragma unroll
    for (int j = 0; j < 4; j++) {
        int col = wn + j * 8 + tig * 2;
        bs[j][0] = __ldg(&bias[col]);  bs[j][1] = __ldg(&bias[col + 1]);
    }
#pragma unroll
    for (int i = 0; i < 4; i++) {
        int rbase = m0 + wm + i * 16 + grp;
#pragma unroll
        for (int half = 0; half < 2; half++) {
            int m = rbase + half * 8;
            if (m >= N_NODES) continue;
#pragma unroll
            for (int j = 0; j < 4; j++) {
                int col = wn + j * 8 + tig * 2;
                float v0 = acc[i][j][half * 2 + 0] + bs[j][0];
                float v1 = acc[i][j][half * 2 + 1] + bs[j][1];
                __half2 h = __floats2half2_rn(v0, v1);
                *(uint32_t*)&g_hlh[(size_t)m * D + col] = *(uint32_t*)&h;
            }
        }
    }
}

// ---------------- gather message + self term + fused BN stats ----------------
// outL[layer][n] = relu(hl[n]+root)/deg[n] + sum_k enorm[k]*relu(hl[src[k]]+edge[k])
__global__ __launch_bounds__(256)
void gather_kernel(int layer, const float* __restrict__ root) {
    __shared__ float shs[8 * 128];
    __shared__ float shq[8 * 128];
    float* out = g_outL + (size_t)layer * ND;
    int wid = threadIdx.x >> 5, lane = threadIdx.x & 31;
    int d4 = lane * 4;
    float4 rt = *(const float4*)&root[d4];
    float4 sum = make_float4(0.f, 0.f, 0.f, 0.f);
    float4 sq  = make_float4(0.f, 0.f, 0.f, 0.f);

    for (int n = blockIdx.x * 8 + wid; n < N_NODES; n += gridDim.x * 8) {
        int start = g_off[n];
        int end = (n < N_NODES - 1) ? g_off[n + 1] : N_EDGES;
        float inv = 1.f / g_deg[n];
        uint2 hp = *(const uint2*)&g_hlh[(size_t)n * D + d4];
        float2 h01 = __half22float2(*(__half2*)&hp.x);
        float2 h23 = __half22float2(*(__half2*)&hp.y);
        float4 acc;
        acc.x = fmaxf(h01.x + rt.x, 0.f) * inv;
        acc.y = fmaxf(h01.y + rt.y, 0.f) * inv;
        acc.z = fmaxf(h23.x + rt.z, 0.f) * inv;
        acc.w = fmaxf(h23.y + rt.w, 0.f) * inv;
        for (int k = start; k < end; k++) {
            int s = g_src[k];
            float nm = g_enorm[k];
            uint2 sp = *(const uint2*)&g_hlh[(size_t)s * D + d4];
            float2 s01 = __half22float2(*(__half2*)&sp.x);
            float2 s23 = __half22float2(*(__half2*)&sp.y);
            uint2 ep = *(const uint2*)&g_edgeh[(size_t)k * D + d4];
            float2 e01 = __half22float2(*(__half2*)&ep.x);
            float2 e23 = __half22float2(*(__half2*)&ep.y);
            acc.x += fmaxf(s01.x + e01.x, 0.f) * nm;
            acc.y += fmaxf(s01.y + e01.y, 0.f) * nm;
            acc.z += fmaxf(s23.x + e23.x, 0.f) * nm;
            acc.w += fmaxf(s23.y + e23.y, 0.f) * nm;
        }
        *(float4*)&out[(size_t)n * D + d4] = acc;
        sum.x += acc.x; sum.y += acc.y; sum.z += acc.z; sum.w += acc.w;
        sq.x += acc.x * acc.x; sq.y += acc.y * acc.y;
        sq.z += acc.z * acc.z; sq.w += acc.w * acc.w;
    }

    *(float4*)&shs[wid * 128 + d4] = sum;
    *(float4*)&shq[wid * 128 + d4] = sq;
    __syncthreads();
    if (threadIdx.x < 128) {
        float s = 0.f, q = 0.f;
#pragma unroll
        for (int w = 0; w < 8; w++) {
            s += shs[w * 128 + threadIdx.x];
            q += shq[w * 128 + threadIdx.x];
        }
        atomicAdd(&g_stats[threadIdx.x], s);
        atomicAdd(&g_stats[D + threadIdx.x], q);
    }
}

// ---------------- batch-norm params ----------------
__global__ void bn_kernel(int layer,
                          const float* __restrict__ gamma, const float* __restrict__ beta) {
    int d = threadIdx.x;
    float* bn = g_bnL + (size_t)layer * 2 * D;
    float mean = g_stats[d] * (1.f / N_NODES);
    float var = g_stats[D + d] * (1.f / N_NODES) - mean * mean;
    float sc = __ldg(&gamma[d]) * rsqrtf(var + BN_EPS);
    bn[d] = sc;
    bn[D + d] = __ldg(&beta[d]) - mean * sc;
}

// ---------------- final: total += sum_l bn_l(outL[l]) (relu for l < L-1) ----------------
__global__ void final_total_kernel(float* __restrict__ total) {
    int lane = threadIdx.x & 31;
    int warp = threadIdx.x >> 5;
    int d4 = lane * 4;
    float4 sc[NLAYER], sh[NLAYER];
#pragma unroll
    for (int l = 0; l < NLAYER; l++) {
        sc[l] = *(const float4*)&g_bnL[l * 2 * D + d4];
        sh[l] = *(const float4*)&g_bnL[l * 2 * D + D + d4];
    }
    for (int n = blockIdx.x * 8 + warp; n < N_NODES; n += gridDim.x * 8) {
        size_t idx = (size_t)n * D + d4;
        float4 t = *(const float4*)&total[idx];
#pragma unroll
        for (int l = 0; l < NLAYER; l++) {
            float4 v = *(const float4*)&g_outL[l * ND + idx];
            float w0 = v.x * sc[l].x + sh[l].x;
            float w1 = v.y * sc[l].y + sh[l].y;
            float w2 = v.z * sc[l].z + sh[l].z;
            float w3 = v.w * sc[l].w + sh[l].w;
            if (l < NLAYER - 1) {
                w0 = fmaxf(w0, 0.f); w1 = fmaxf(w1, 0.f);
                w2 = fmaxf(w2, 0.f); w3 = fmaxf(w3, 0.f);
            }
            t.x += w0; t.y += w1; t.z += w2; t.w += w3;
        }
        *(float4*)&total[idx] = t;
    }
}

// ---------------- launch ----------------
extern "C" void kernel_launch(void* const* d_in, const int* in_sizes, int n_in,
                              void* d_out, int out_size) {
    const int* x     = (const int*)d_in[0];
    const int* ei    = (const int*)d_in[1];
    const int* row   = ei;            // edge_index[0] : source j
    const int* col   = ei + N_EDGES;  // edge_index[1] : target i
    const int* ea    = (const int*)d_in[2];
    const float* at  = (const float*)d_in[3];
    const float* bt  = (const float*)d_in[4];
    const float* W   = (const float*)d_in[5];
    const float* b   = (const float*)d_in[6];
    const float* root  = (const float*)d_in[7];
    const float* gamma = (const float*)d_in[8];
    const float* beta  = (const float*)d_in[9];
    float* total = (float*)d_out;

    const int nscan = (N_NODES + 255) / 256;   // 782

    // Launch order puts the layer-0 GEMM 4th so the ncu capture window hits it.
    encode_atoms_kernel<<<(N_NODES + 3) / 4, 128>>>(x, at, total);
    init_kernel<<<1024, 256>>>();
    deg_acc_kernel<<<1024, 256>>>(row);
    gemm_tc_kernel<<<(N_NODES + 127) / 128, 256>>>(0, W, b);          // layer 0 GEMM
    indeg_acc_kernel<<<1024, 256>>>(col);
    scan1_kernel<<<nscan, 256>>>();
    scan2_kernel<<<1, 1024>>>(nscan);
    scan3_kernel<<<nscan, 256>>>();
    fill_kernel<<<1024, 256>>>(row, col);
    encode_bonds_kernel<<<(N_EDGES + 3) / 4, 128>>>(ea, bt);

    for (int l = 0; l < NLAYER; l++) {
        if (l > 0)
            gemm_tc_kernel<<<(N_NODES + 127) / 128, 256>>>(
                l, W + (size_t)l * D * D, b + (size_t)l * D);
        gather_kernel<<<2048, 256>>>(l, root + (size_t)l * D);
        bn_kernel<<<1, 128>>>(l, gamma + (size_t)l * D, beta + (size_t)l * D);
    }
    final_total_kernel<<<2048, 256>>>(total);
}